// round 12
// baseline (speedup 1.0000x reference)
#include <cuda_runtime.h>
#include <cuda_fp16.h>
#include <cstdint>

#define B_  8
#define T_  2048
#define C_  1024
#define NH  16
#define HS  64
#define NG  8
#define GT  256
#define LQ  257

// ---------------- device scratch ----------------
__device__ float g_q[B_*NH*NG*GT*HS];
__device__ float g_k[B_*NH*NG*GT*HS];
__device__ float g_v[B_*NH*NG*GT*HS];
__device__ float g_qm[B_*NH*NG*HS];
__device__ float g_km[B_*NH*NG*HS];
__device__ float g_vm[B_*NH*NG*HS];
__device__ float g_attm[B_*NH*NG*HS];
__device__ __half h_xr[B_*T_*C_];         // x, fp16 plain row-major
__device__ __half h_xo[B_*T_*C_];         // attn out, fp16 plain row-major
__device__ __half h_War[3*C_*C_];         // W_attn^T [3072][1024] fp16
__device__ __half h_WpR[C_*C_];           // W_proj^T [1024][1024] fp16

// attention-internal tf32 pair interleave
__device__ __forceinline__ int perm8(int k)  { return ((k & 3) << 1) | ((k >> 2) & 1); }
__device__ __forceinline__ int kperm(int k)  { return (k & ~7) | perm8(k & 7); }

__device__ __forceinline__ float tf32r(float x) {
    unsigned r;
    asm("cvt.rna.tf32.f32 %0, %1;" : "=r"(r) : "f"(x));
    return __uint_as_float(r);
}

__device__ __forceinline__ uint32_t smem_u32(const void* p) {
    uint32_t a;
    asm("{ .reg .u64 t; cvta.to.shared.u64 t, %1; cvt.u32.u64 %0, t; }" : "=r"(a) : "l"(p));
    return a;
}

__device__ __forceinline__ void cp16(uint32_t dst, const void* src) {
    asm volatile("cp.async.cg.shared.global [%0], [%1], 16;\n" :: "r"(dst), "l"(src));
}
#define CP_COMMIT() asm volatile("cp.async.commit_group;\n" ::: "memory")
#define CP_WAIT(n)  asm volatile("cp.async.wait_group %0;\n" :: "n"(n) : "memory")

__device__ __forceinline__ void ldmx4(uint32_t* r, uint32_t addr) {
    asm volatile("ldmatrix.sync.aligned.m8n8.x4.shared.b16 {%0,%1,%2,%3}, [%4];"
                 : "=r"(r[0]), "=r"(r[1]), "=r"(r[2]), "=r"(r[3]) : "r"(addr));
}

__device__ __forceinline__ void mma_f16(float& c0, float& c1, float& c2, float& c3,
                                        uint32_t a0, uint32_t a1, uint32_t a2, uint32_t a3,
                                        uint32_t b0, uint32_t b1) {
    asm volatile(
        "mma.sync.aligned.m16n8k16.row.col.f32.f16.f16.f32 "
        "{%0,%1,%2,%3}, {%4,%5,%6,%7}, {%8,%9}, {%0,%1,%2,%3};\n"
        : "+f"(c0), "+f"(c1), "+f"(c2), "+f"(c3)
        : "r"(a0), "r"(a1), "r"(a2), "r"(a3), "r"(b0), "r"(b1));
}

__device__ __forceinline__ void mma_tf32(float& c0, float& c1, float& c2, float& c3,
                                         float a0, float a1, float a2, float a3,
                                         float b0, float b1) {
    asm volatile(
        "mma.sync.aligned.m16n8k8.row.col.f32.tf32.tf32.f32 "
        "{%0,%1,%2,%3}, {%4,%5,%6,%7}, {%8,%9}, {%0,%1,%2,%3};\n"
        : "+f"(c0), "+f"(c1), "+f"(c2), "+f"(c3)
        : "r"(__float_as_uint(a0)), "r"(__float_as_uint(a1)),
          "r"(__float_as_uint(a2)), "r"(__float_as_uint(a3)),
          "r"(__float_as_uint(b0)), "r"(__float_as_uint(b1)));
}

// ---------------- conversion kernels (plain layouts) ----------------
__global__ void cvt_x_kernel(const float* __restrict__ src) {
    size_t base = ((size_t)blockIdx.x * 256 + threadIdx.x) * 8;
    float4 v0 = *reinterpret_cast<const float4*>(src + base);
    float4 v1 = *reinterpret_cast<const float4*>(src + base + 4);
    __half2 h[4];
    h[0] = __floats2half2_rn(v0.x, v0.y);
    h[1] = __floats2half2_rn(v0.z, v0.w);
    h[2] = __floats2half2_rn(v1.x, v1.y);
    h[3] = __floats2half2_rn(v1.z, v1.w);
    *reinterpret_cast<uint4*>(h_xr + base) = *reinterpret_cast<uint4*>(h);
}

__global__ void cvt_W_kernel(const float* __restrict__ W, int N, int which) {
    __half* Wt = (which == 1) ? h_War : h_WpR;
    __shared__ float tile[32][33];
    int bx = blockIdx.x * 32;   // n
    int by = blockIdx.y * 32;   // k
    int tx = threadIdx.x & 31, ty = threadIdx.x >> 5;
#pragma unroll
    for (int yy = ty; yy < 32; yy += 8)
        tile[yy][tx] = W[(size_t)(by + yy) * N + bx + tx];
    __syncthreads();
#pragma unroll
    for (int yy = ty; yy < 32; yy += 8) {
        int n = bx + yy, k = by + tx;
        Wt[(size_t)n * 1024 + k] = __float2half_rn(tile[tx][yy]);
    }
}

// ---------------- fp16 GEMM: 128x128 CTA, 2x2 warps of 64x64, ldmatrix ----------------
#define BK 32
#define KCHUNKS 32
#define STAGES 6
#define STG_BYTES 16384            // A 8KB + B 8KB

__global__ __launch_bounds__(128, 2)
void gemm_f16_kernel(float* __restrict__ Cout, int mode) {
    extern __shared__ __align__(16) char smc[];
    const uint32_t stg_b = smem_u32(smc);

    const __half* __restrict__ Ah = (mode == 0) ? h_xr  : h_xo;
    const __half* __restrict__ Bh = (mode == 0) ? h_War : h_WpR;

    const int tid  = threadIdx.x;
    const int warp = tid >> 5;
    const int lane = tid & 31;
    const int wm   = warp & 1;
    const int wn   = warp >> 1;
    const int bm   = blockIdx.x * 128;
    const int bn   = blockIdx.y * 128;

    float acc[4][8][4];
#pragma unroll
    for (int mt = 0; mt < 4; mt++)
#pragma unroll
        for (int nt = 0; nt < 8; nt++)
#pragma unroll
            for (int i = 0; i < 4; i++) acc[mt][nt][i] = 0.f;

    const int csw = (tid >> 1) & 3;   // copy swizzle for row tid

    auto issue_copy = [&](int c, int s) {
        const int k0 = c * BK;
        const uint32_t sa = stg_b + (uint32_t)(s * STG_BYTES);
        const uint32_t sb = sa + 8192u;
        const __half* Asrc = Ah + (size_t)(bm + tid) * 1024 + k0;
        const __half* Bsrc = Bh + (size_t)(bn + tid) * 1024 + k0;
#pragma unroll
        for (int g = 0; g < 4; g++) {
            uint32_t d = (uint32_t)(tid * 64 + ((g ^ csw) << 4));
            cp16(sa + d, Asrc + g * 8);
            cp16(sb + d, Bsrc + g * 8);
        }
        CP_COMMIT();
    };

#pragma unroll
    for (int p = 0; p < 5; p++) issue_copy(p, p);

    const int t8 = lane & 7;
    const int j  = lane >> 3;
    const int sw = t8 >> 1;
    // A: row = wm*64 + mt*16 + t8 + 8*(j&1), gran = (2*g16 + (j>>1)) ^ sw
    // B: row = wn*64 + ntp*16 + t8 + 8*(j>>1), gran = (2*g16 + (j&1)) ^ sw
    const int arow_off = wm * 64 + t8 + 8 * (j & 1);
    const int brow_off = wn * 64 + t8 + 8 * (j >> 1);
    const int agr = j >> 1;
    const int bgr = j & 1;

    int stage = 0;
    for (int c = 0; c < KCHUNKS; c++) {
        CP_WAIT(4);
        __syncthreads();
        if (c + 5 < KCHUNKS) {
            int ns = stage + 5; if (ns >= STAGES) ns -= STAGES;
            issue_copy(c + 5, ns);
        } else {
            CP_COMMIT();   // empty group keeps WAIT(4) semantics
        }

        const uint32_t As = stg_b + (uint32_t)(stage * STG_BYTES);
        const uint32_t Bs = As + 8192u;

#pragma unroll
        for (int g16 = 0; g16 < 2; g16++) {
            uint32_t a[4][4], br[4][4];
#pragma unroll
            for (int mt = 0; mt < 4; mt++)
                ldmx4(a[mt], As + (uint32_t)((arow_off + mt * 16) * 64
                                             + (((2 * g16 + agr) ^ sw) << 4)));
#pragma unroll
            for (int ntp = 0; ntp < 4; ntp++)
                ldmx4(br[ntp], Bs + (uint32_t)((brow_off + ntp * 16) * 64
                                               + (((2 * g16 + bgr) ^ sw) << 4)));
#pragma unroll
            for (int mt = 0; mt < 4; mt++)
#pragma unroll
                for (int nt = 0; nt < 8; nt++)
                    mma_f16(acc[mt][nt][0], acc[mt][nt][1], acc[mt][nt][2], acc[mt][nt][3],
                            a[mt][0], a[mt][1], a[mt][2], a[mt][3],
                            br[nt >> 1][2 * (nt & 1)], br[nt >> 1][2 * (nt & 1) + 1]);
        }
        stage++; if (stage >= STAGES) stage = 0;
    }

    const int lr = lane >> 2;
    const int lc = lane & 3;
    const int N = (mode == 0) ? 3 * C_ : C_;
#pragma unroll
    for (int mt = 0; mt < 4; mt++) {
#pragma unroll
        for (int i2 = 0; i2 < 2; i2++) {
            const int r = bm + wm * 64 + mt * 16 + lr + i2 * 8;
#pragma unroll
            for (int nt = 0; nt < 8; nt++) {
                const int c = bn + wn * 64 + nt * 8 + lc * 2;
                float2 v = make_float2(acc[mt][nt][i2 * 2], acc[mt][nt][i2 * 2 + 1]);
                if (mode == 0) {
                    const int which = c >> 10, cc = c & 1023;
                    const int h = cc >> 6, d0 = cc & 63;
                    const int b = r >> 11, tg = r & 2047, g = tg >> 8, t = tg & 255;
                    float* base = (which == 0) ? g_q : (which == 1) ? g_k : g_v;
                    *reinterpret_cast<float2*>(
                        base + ((((size_t)b * NH + h) * NG + g) * GT + t) * HS + d0) = v;
                } else {
                    *reinterpret_cast<float2*>(Cout + (size_t)r * N + c) = v;
                }
            }
        }
    }
}

// ---------------- HMMA flash attention over 257 tokens ----------------
#define KS_OFF  0
#define KS_STR  68
#define VT_OFF  17476
#define VT_STR  264
#define STR_OFF 34372
#define QM_OFF  43076
#define WB_OFF  43144
#define ATT_F   43408

__global__ __launch_bounds__(256)
void attn_kernel() {
    extern __shared__ float sm[];
    const int id = blockIdx.x;
    const int g = id & 7, h = (id >> 3) & 15, b = id >> 7;
    const int tid = threadIdx.x;
    const int warp = tid >> 5, lane = tid & 31;
    const int lr = lane >> 2, lc = lane & 3;

    const size_t off = (size_t)id * (GT * HS);

    for (int idx = tid; idx < GT * HS; idx += 256) {
        int t = idx >> 6, d = idx & 63;
        sm[KS_OFF + t * KS_STR + kperm(d)] = tf32r(g_k[off + idx]);
        sm[VT_OFF + d * VT_STR + kperm(t)] = tf32r(g_v[off + idx]);
    }
    __syncthreads();

    {
        int which = tid >> 6;
        int d = tid & 63;
        if (which == 0) {
            float s = 0.f;
#pragma unroll 8
            for (int t = 0; t < GT; t++) s += g_q[off + t * HS + d];
            float m = s * (1.f / 256.f);
            g_qm[(size_t)id * HS + d] = m;
            sm[QM_OFF + kperm(d)] = tf32r(m);
        } else if (which == 1) {
            float s = 0.f;
#pragma unroll 8
            for (int t = 0; t < GT; t++) s += g_k[off + t * HS + d];
            float m = s * (1.f / 256.f);
            g_km[(size_t)id * HS + d] = m;
            sm[KS_OFF + 256 * KS_STR + kperm(d)] = tf32r(m);
        } else if (which == 2) {
            float s = 0.f;
            const float* vp = sm + VT_OFF + d * VT_STR;
#pragma unroll 16
            for (int t = 0; t < GT; t += 4) {
                float4 v = *reinterpret_cast<const float4*>(vp + t);
                s += v.x + v.y + v.z + v.w;
            }
            float m = s * (1.f / 256.f);
            sm[VT_OFF + d * VT_STR + 256] = tf32r(m);
#pragma unroll
            for (int p = 1; p < 8; p++) sm[VT_OFF + d * VT_STR + 256 + p] = 0.f;
        }
    }

    float* strip = sm + STR_OFF + warp * 16 * KS_STR;

#pragma unroll 1
    for (int qt = 0; qt < 2; qt++) {
        const int qb = qt * 128;
        const int r0 = qb + warp * 16 + lr;
        const int nchunks = qt ? 4 : 2;

        float qa[8][4];
        const float* qrow0 = g_q + off + (size_t)r0 * HS;
        const float* qrow1 = qrow0 + 8 * HS;
#pragma unroll
        for (int ds = 0; ds < 8; ds++) {
            qa[ds][0] = tf32r(qrow0[ds * 8 + lc]);
            qa[ds][1] = tf32r(qrow1[ds * 8 + lc]);
            qa[ds][2] = tf32r(qrow0[ds * 8 + lc + 4]);
            qa[ds][3] = tf32r(qrow1[ds * 8 + lc + 4]);
        }

        float m0 = -1e30f, m1 = -1e30f, l0 = 0.f, l1 = 0.f;
        float o[8][4];
#pragma unroll
        for (int nt = 0; nt < 8; nt++)
#pragma unroll
            for (int i = 0; i < 4; i++) o[nt][i] = 0.f;

#pragma unroll 1
        for (int kc = 0; kc < nchunks; kc++) {
            const int kbase = kc * 64;

            float s[8][4];
#pragma unroll
            for (int nt = 0; nt < 8; nt++) { s[nt][0] = s[nt][1] = s[nt][2] = s[nt][3] = 0.f; }
#pragma unroll
            for (int nt = 0; nt < 8; nt++) {
                const float* krow = sm + KS_OFF + (kbase + nt * 8 + lr) * KS_STR;
#pragma unroll
                for (int ds = 0; ds < 8; ds++) {
                    float2 bv = *reinterpret_cast<const float2*>(krow + ds * 8 + 2 * lc);
                    mma_tf32(s[nt][0], s[nt][1], s[nt][2], s[nt][3],
                             qa[ds][0], qa[ds][1], qa[ds][2], qa[ds][3], bv.x, bv.y);
                }
            }

            float mx0 = -1e30f, mx1 = -1e30f;
#pragma unroll
            for (int nt = 0; nt < 8; nt++) {
                const int j0 = kbase + nt * 8 + 2 * lc;
                const int j1 = j0 + 1;
                float v0 = s[nt][0] * 0.125f; if (j0 > r0)     v0 = -1e30f;
                float v1 = s[nt][1] * 0.125f; if (j1 > r0)     v1 = -1e30f;
                float v2 = s[nt][2] * 0.125f; if (j0 > r0 + 8) v2 = -1e30f;
                float v3 = s[nt][3] * 0.125f; if (j1 > r0 + 8) v3 = -1e30f;
                s[nt][0] = v0; s[nt][1] = v1; s[nt][2] = v2; s[nt][3] = v3;
                mx0 = fmaxf(mx0, fmaxf(v0, v1));
                mx1 = fmaxf(mx1, fmaxf(v2, v3));
            }
            mx0 = fmaxf(mx0, __shfl_xor_sync(0xffffffffu, mx0, 1));
            mx0 = fmaxf(mx0, __shfl_xor_sync(0xffffffffu, mx0, 2));
            mx1 = fmaxf(mx1, __shfl_xor_sync(0xffffffffu, mx1, 1));
            mx1 = fmaxf(mx1, __shfl_xor_sync(0xffffffffu, mx1, 2));

            const float nm0 = fmaxf(m0, mx0);
            const float nm1 = fmaxf(m1, mx1);
            const float f0 = __expf(m0 - nm0);
            const float f1 = __expf(m1 - nm1);
            m0 = nm0; m1 = nm1;

            float rs0 = 0.f, rs1 = 0.f;
#pragma unroll
            for (int nt = 0; nt < 8; nt++) {
                float p0 = __expf(s[nt][0] - nm0);
                float p1 = __expf(s[nt][1] - nm0);
                float p2 = __expf(s[nt][2] - nm1);
                float p3 = __expf(s[nt][3] - nm1);
                rs0 += p0 + p1; rs1 += p2 + p3;
                const int c0 = nt * 8 + perm8(2 * lc);
                const int c1 = nt * 8 + perm8(2 * lc + 1);
                strip[lr * KS_STR + c0]       = tf32r(p0);
                strip[lr * KS_STR + c1]       = tf32r(p1);
                strip[(lr + 8) * KS_STR + c0] = tf32r(p2);
                strip[(lr + 8) * KS_STR + c1] = tf32r(p3);
            }
            rs0 += __shfl_xor_sync(0xffffffffu, rs0, 1);
            rs0 += __shfl_xor_sync(0xffffffffu, rs0, 2);
            rs1 += __shfl_xor_sync(0xffffffffu, rs1, 1);
            rs1 += __shfl_xor_sync(0xffffffffu, rs1, 2);
            l0 = l0 * f0 + rs0;
            l1 = l1 * f1 + rs1;
#pragma unroll
            for (int nt = 0; nt < 8; nt++) {
                o[nt][0] *= f0; o[nt][1] *= f0;
                o[nt][2] *= f1; o[nt][3] *= f1;
            }
            __syncwarp();

            float pa[8][4];
#pragma unroll
            for (int ks = 0; ks < 8; ks++) {
                float2 lo = *reinterpret_cast<const float2*>(strip + lr * KS_STR + ks * 8 + 2 * lc);
                float2 hi = *reinterpret_cast<const float2*>(strip + (lr + 8) * KS_STR + ks * 8 + 2 * lc);
                pa[ks][0] = lo.x; pa[ks][1] = hi.x; pa[ks][2] = lo.y; pa[ks][3] = hi.y;
            }
#pragma unroll
            for (int nt = 0; nt < 8; nt++) {
                const float* vrow = sm + VT_OFF + (nt * 8 + lr) * VT_STR + kbase;
#pragma unroll
                for (int ks = 0; ks < 8; ks++) {
                    float2 bv = *reinterpret_cast<const float2*>(vrow + ks * 8 + 2 * lc);
                    mma_tf32(o[nt][0], o[nt][1], o[nt][2], o[nt][3],
                             pa[ks][0], pa[ks][1], pa[ks][2], pa[ks][3], bv.x, bv.y);
                }
            }
            __syncwarp();
        }

        // finalize: write plain fp16 h_xo (proj GEMM's A operand)
        const float inv0 = 1.f / l0;
        const float inv1 = 1.f / l1;
        __half* x0 = h_xo + ((size_t)b * T_ + g * GT + r0) * C_ + h * HS;
        __half* x1 = x0 + (size_t)8 * C_;
#pragma unroll
        for (int nt = 0; nt < 8; nt++) {
            const int p = nt * 8 + 2 * lc;
            *reinterpret_cast<__half2*>(x0 + p) = __floats2half2_rn(o[nt][0] * inv0, o[nt][1] * inv0);
            *reinterpret_cast<__half2*>(x1 + p) = __floats2half2_rn(o[nt][2] * inv1, o[nt][3] * inv1);
        }
    }

    __syncthreads();

    if (warp == 0) {
        float* wbuf = sm + WB_OFF;
        if (lane < 7) wbuf[257 + lane] = 0.f;
        const float* qm = sm + QM_OFF;
        float mx = -1e30f;
        float sc[9];
        for (int j = lane, u = 0; j < LQ; j += 32, u++) {
            const float4* kp = reinterpret_cast<const float4*>(sm + KS_OFF + j * KS_STR);
            const float4* qp = reinterpret_cast<const float4*>(qm);
            float s = 0.f;
#pragma unroll
            for (int dd = 0; dd < 16; dd++) {
                float4 kv = kp[dd], qv = qp[dd];
                s += qv.x * kv.x + qv.y * kv.y + qv.z * kv.z + qv.w * kv.w;
            }
            s *= 0.125f;
            sc[u] = s;
            mx = fmaxf(mx, s);
        }
#pragma unroll
        for (int o2 = 16; o2; o2 >>= 1) mx = fmaxf(mx, __shfl_xor_sync(0xffffffffu, mx, o2));
        float sum = 0.f;
        for (int j = lane, u = 0; j < LQ; j += 32, u++) {
            float e = __expf(sc[u] - mx);
            wbuf[kperm(j)] = e;
            sum += e;
        }
#pragma unroll
        for (int o2 = 16; o2; o2 >>= 1) sum += __shfl_xor_sync(0xffffffffu, sum, o2);
        const float inv = 1.f / sum;
        __syncwarp();
#pragma unroll
        for (int dh = 0; dh < 2; dh++) {
            const int d = lane + dh * 32;
            const float* vp = sm + VT_OFF + d * VT_STR;
            float acc = 0.f;
#pragma unroll 8
            for (int j = 0; j < 264; j += 4) {
                float4 w = *reinterpret_cast<const float4*>(wbuf + j);
                float4 v = *reinterpret_cast<const float4*>(vp + j);
                acc += w.x * v.x + w.y * v.y + w.z * v.z + w.w * v.w;
            }
            g_attm[(size_t)id * HS + d] = acc * inv;
        }
    }
}

// ---------------- level-2 tiny 7x7 causal attention + y outputs ----------------
__global__ void second_kernel(float* __restrict__ out) {
    __shared__ float q7[7][64], k7[7][64], a7[7][64];
    __shared__ float S[7][8], W[7][8];
    const int id = blockIdx.x;
    const int tid = threadIdx.x;

    for (int idx = tid; idx < 7 * 64; idx += 64) {
        int j = idx >> 6, d = idx & 63;
        q7[j][d] = g_qm[((size_t)id * NG + j) * HS + d];
        k7[j][d] = g_km[((size_t)id * NG + j) * HS + d];
        a7[j][d] = g_attm[((size_t)id * NG + j) * HS + d];
    }
    __syncthreads();

    if (tid < 28) {
        int p = tid, j = 0;
        while ((j + 1) * (j + 2) / 2 <= p) j++;
        int jp = p - j * (j + 1) / 2;
        float s = 0.f;
#pragma unroll
        for (int dd = 0; dd < 64; dd++) s += q7[j][dd] * k7[jp][dd];
        S[j][jp] = s * 0.125f;
    }
    __syncthreads();

    if (tid < 7) {
        int j = tid;
        float mx = -1e30f;
        for (int jp = 0; jp <= j; jp++) mx = fmaxf(mx, S[j][jp]);
        float sum = 0.f;
        for (int jp = 0; jp <= j; jp++) { float e = __expf(S[j][jp] - mx); W[j][jp] = e; sum += e; }
        float inv = 1.f / sum;
        for (int jp = 0; jp <= j; jp++) W[j][jp] *= inv;
    }
    __syncthreads();

    const size_t yq_off = (size_t)B_ * T_ * C_;
    const size_t ylen   = (size_t)B_ * NH * 7 * HS;
    int d = tid;
    for (int j = 0; j < 7; j++) {
        float acc = 0.f;
        for (int jp = 0; jp <= j; jp++) acc += W[j][jp] * a7[jp][d];
        size_t o = ((size_t)id * 7 + j) * HS + d;
        out[yq_off            + o] = q7[j][d];
        out[yq_off +     ylen + o] = k7[j][d];
        out[yq_off + 2 * ylen + o] = acc;
    }
}

// ---------------- launch ----------------
extern "C" void kernel_launch(void* const* d_in, const int* in_sizes, int n_in,
                              void* d_out, int out_size) {
    (void)in_sizes; (void)n_in; (void)out_size;
    const float* x      = (const float*)d_in[0];
    const float* W_attn = (const float*)d_in[1];
    const float* W_proj = (const float*)d_in[2];
    float* out = (float*)d_out;

    cvt_x_kernel<<<B_*T_*C_/2048, 256>>>(x);
    cvt_W_kernel<<<dim3(96, 32), 256>>>(W_attn, 3 * C_, 1);
    cvt_W_kernel<<<dim3(32, 32), 256>>>(W_proj, C_, 2);

    const int gemm_smem = STAGES * STG_BYTES;   // 98304
    cudaFuncSetAttribute(gemm_f16_kernel, cudaFuncAttributeMaxDynamicSharedMemorySize, gemm_smem);

    // qkv = x @ W_attn  (M=16384, N=3072)
    gemm_f16_kernel<<<dim3(128, 24), 128, gemm_smem>>>(nullptr, 0);

    const int att_smem = ATT_F * (int)sizeof(float);
    cudaFuncSetAttribute(attn_kernel, cudaFuncAttributeMaxDynamicSharedMemorySize, att_smem);
    attn_kernel<<<B_ * NH * NG, 256, att_smem>>>();

    second_kernel<<<B_ * NH, 64>>>(out);

    // out = xo @ W_proj  (M=16384, N=1024)
    gemm_f16_kernel<<<dim3(128, 8), 128, gemm_smem>>>(out, 1);
}

// round 13
// speedup vs baseline: 1.2176x; 1.2176x over previous
#include <cuda_runtime.h>
#include <cuda_fp16.h>
#include <cstdint>

#define B_  8
#define T_  2048
#define C_  1024
#define NH  16
#define HS  64
#define NG  8
#define GT  256
#define LQ  257

// ---------------- device scratch ----------------
__device__ float g_q[B_*NH*NG*GT*HS];
__device__ float g_k[B_*NH*NG*GT*HS];
__device__ float g_v[B_*NH*NG*GT*HS];
__device__ float g_qm[B_*NH*NG*HS];
__device__ float g_km[B_*NH*NG*HS];
__device__ float g_vm[B_*NH*NG*HS];
__device__ float g_attm[B_*NH*NG*HS];
__device__ __half h_xr[B_*T_*C_];         // x, fp16 plain row-major
__device__ __half h_xo[B_*T_*C_];         // attn out, fp16 plain row-major
__device__ __half h_War[3*C_*C_];         // W_attn^T [3072][1024] fp16
__device__ __half h_WpR[C_*C_];           // W_proj^T [1024][1024] fp16

// attention-internal tf32 pair interleave
__device__ __forceinline__ int perm8(int k)  { return ((k & 3) << 1) | ((k >> 2) & 1); }
__device__ __forceinline__ int kperm(int k)  { return (k & ~7) | perm8(k & 7); }

__device__ __forceinline__ float tf32r(float x) {
    unsigned r;
    asm("cvt.rna.tf32.f32 %0, %1;" : "=r"(r) : "f"(x));
    return __uint_as_float(r);
}

__device__ __forceinline__ uint32_t smem_u32(const void* p) {
    uint32_t a;
    asm("{ .reg .u64 t; cvta.to.shared.u64 t, %1; cvt.u32.u64 %0, t; }" : "=r"(a) : "l"(p));
    return a;
}

__device__ __forceinline__ void cp16(uint32_t dst, const void* src) {
    asm volatile("cp.async.cg.shared.global [%0], [%1], 16;\n" :: "r"(dst), "l"(src));
}
#define CP_COMMIT() asm volatile("cp.async.commit_group;\n" ::: "memory")
#define CP_WAIT(n)  asm volatile("cp.async.wait_group %0;\n" :: "n"(n) : "memory")

__device__ __forceinline__ void ldmx4(uint32_t* r, uint32_t addr) {
    asm volatile("ldmatrix.sync.aligned.m8n8.x4.shared.b16 {%0,%1,%2,%3}, [%4];"
                 : "=r"(r[0]), "=r"(r[1]), "=r"(r[2]), "=r"(r[3]) : "r"(addr));
}

__device__ __forceinline__ void mma_f16(float& c0, float& c1, float& c2, float& c3,
                                        uint32_t a0, uint32_t a1, uint32_t a2, uint32_t a3,
                                        uint32_t b0, uint32_t b1) {
    asm volatile(
        "mma.sync.aligned.m16n8k16.row.col.f32.f16.f16.f32 "
        "{%0,%1,%2,%3}, {%4,%5,%6,%7}, {%8,%9}, {%0,%1,%2,%3};\n"
        : "+f"(c0), "+f"(c1), "+f"(c2), "+f"(c3)
        : "r"(a0), "r"(a1), "r"(a2), "r"(a3), "r"(b0), "r"(b1));
}

__device__ __forceinline__ void mma_tf32(float& c0, float& c1, float& c2, float& c3,
                                         float a0, float a1, float a2, float a3,
                                         float b0, float b1) {
    asm volatile(
        "mma.sync.aligned.m16n8k8.row.col.f32.tf32.tf32.f32 "
        "{%0,%1,%2,%3}, {%4,%5,%6,%7}, {%8,%9}, {%0,%1,%2,%3};\n"
        : "+f"(c0), "+f"(c1), "+f"(c2), "+f"(c3)
        : "r"(__float_as_uint(a0)), "r"(__float_as_uint(a1)),
          "r"(__float_as_uint(a2)), "r"(__float_as_uint(a3)),
          "r"(__float_as_uint(b0)), "r"(__float_as_uint(b1)));
}

// ---------------- conversion kernels (plain layouts) ----------------
__global__ void cvt_x_kernel(const float* __restrict__ src) {
    size_t base = ((size_t)blockIdx.x * 256 + threadIdx.x) * 8;
    float4 v0 = *reinterpret_cast<const float4*>(src + base);
    float4 v1 = *reinterpret_cast<const float4*>(src + base + 4);
    __half2 h[4];
    h[0] = __floats2half2_rn(v0.x, v0.y);
    h[1] = __floats2half2_rn(v0.z, v0.w);
    h[2] = __floats2half2_rn(v1.x, v1.y);
    h[3] = __floats2half2_rn(v1.z, v1.w);
    *reinterpret_cast<uint4*>(h_xr + base) = *reinterpret_cast<uint4*>(h);
}

__global__ void cvt_W_kernel(const float* __restrict__ W, int N, int which) {
    __half* Wt = (which == 1) ? h_War : h_WpR;
    __shared__ float tile[32][33];
    int bx = blockIdx.x * 32;   // n
    int by = blockIdx.y * 32;   // k
    int tx = threadIdx.x & 31, ty = threadIdx.x >> 5;
#pragma unroll
    for (int yy = ty; yy < 32; yy += 8)
        tile[yy][tx] = W[(size_t)(by + yy) * N + bx + tx];
    __syncthreads();
#pragma unroll
    for (int yy = ty; yy < 32; yy += 8) {
        int n = bx + yy, k = by + tx;
        Wt[(size_t)n * 1024 + k] = __float2half_rn(tile[tx][yy]);
    }
}

// ---------------- fp16 GEMM: 128x128 CTA, 2x4 warps of 64x32, ldmatrix ----------------
#define BK 32
#define KCHUNKS 32
#define STAGES 4
#define STG_BYTES 16384            // A 8KB + B 8KB

__global__ __launch_bounds__(256, 2)
void gemm_f16_kernel(float* __restrict__ Cout, int mode) {
    extern __shared__ __align__(16) char smc[];
    const uint32_t stg_b = smem_u32(smc);

    const __half* __restrict__ Ah = (mode == 0) ? h_xr  : h_xo;
    const __half* __restrict__ Bh = (mode == 0) ? h_War : h_WpR;

    const int tid  = threadIdx.x;
    const int warp = tid >> 5;
    const int lane = tid & 31;
    const int wm   = warp & 1;      // 2 warps along M (64 each)
    const int wn   = warp >> 1;     // 4 warps along N (32 each)
    const int bm   = blockIdx.x * 128;
    const int bn   = blockIdx.y * 128;

    float acc[4][4][4];
#pragma unroll
    for (int mt = 0; mt < 4; mt++)
#pragma unroll
        for (int nt = 0; nt < 4; nt++)
#pragma unroll
            for (int i = 0; i < 4; i++) acc[mt][nt][i] = 0.f;

    // copy: 256 threads, row = tid>>1, each thread 2 granules of A and B
    const int crow = tid >> 1;
    const int cg0  = (tid & 1) * 2;
    const int csw  = (crow >> 1) & 3;

    auto issue_copy = [&](int c, int s) {
        const int k0 = c * BK;
        const uint32_t sa = stg_b + (uint32_t)(s * STG_BYTES);
        const uint32_t sb = sa + 8192u;
        const __half* Asrc = Ah + (size_t)(bm + crow) * 1024 + k0;
        const __half* Bsrc = Bh + (size_t)(bn + crow) * 1024 + k0;
#pragma unroll
        for (int u = 0; u < 2; u++) {
            int g = cg0 + u;
            uint32_t d = (uint32_t)(crow * 64 + ((g ^ csw) << 4));
            cp16(sa + d, Asrc + g * 8);
            cp16(sb + d, Bsrc + g * 8);
        }
        CP_COMMIT();
    };

    issue_copy(0, 0);
    issue_copy(1, 1);
    issue_copy(2, 2);

    // ldmatrix lane mapping (verified in round 12)
    const int t8 = lane & 7;
    const int j  = lane >> 3;
    const int sw = t8 >> 1;
    const int arow_base = wm * 64 + 8 * (j & 1) + t8;
    const int brow_base = wn * 32 + 8 * (j >> 1) + t8;
    const int agr = j >> 1;
    const int bgr = j & 1;

    int stage = 0;
    for (int c = 0; c < KCHUNKS; c++) {
        if (c + 2 < KCHUNKS)      { CP_WAIT(2); }
        else if (c + 1 < KCHUNKS) { CP_WAIT(1); }
        else                      { CP_WAIT(0); }
        __syncthreads();

        if (c + 3 < KCHUNKS) {
            int ns = stage + 3; if (ns >= STAGES) ns -= STAGES;
            issue_copy(c + 3, ns);
        }

        const uint32_t As = stg_b + (uint32_t)(stage * STG_BYTES);
        const uint32_t Bs = As + 8192u;

#pragma unroll
        for (int g16 = 0; g16 < 2; g16++) {
            uint32_t a[4][4], br[2][4];
#pragma unroll
            for (int mt = 0; mt < 4; mt++)
                ldmx4(a[mt], As + (uint32_t)((arow_base + mt * 16) * 64
                                             + (((2 * g16 + agr) ^ sw) << 4)));
#pragma unroll
            for (int ntp = 0; ntp < 2; ntp++)
                ldmx4(br[ntp], Bs + (uint32_t)((brow_base + ntp * 16) * 64
                                               + (((2 * g16 + bgr) ^ sw) << 4)));
#pragma unroll
            for (int mt = 0; mt < 4; mt++)
#pragma unroll
                for (int nt = 0; nt < 4; nt++)
                    mma_f16(acc[mt][nt][0], acc[mt][nt][1], acc[mt][nt][2], acc[mt][nt][3],
                            a[mt][0], a[mt][1], a[mt][2], a[mt][3],
                            br[nt >> 1][2 * (nt & 1)], br[nt >> 1][2 * (nt & 1) + 1]);
        }
        stage++; if (stage >= STAGES) stage = 0;
    }

    const int lr = lane >> 2;
    const int lc = lane & 3;
    const int N = (mode == 0) ? 3 * C_ : C_;
#pragma unroll
    for (int mt = 0; mt < 4; mt++) {
#pragma unroll
        for (int i2 = 0; i2 < 2; i2++) {
            const int r = bm + wm * 64 + mt * 16 + lr + i2 * 8;
#pragma unroll
            for (int nt = 0; nt < 4; nt++) {
                const int c = bn + wn * 32 + nt * 8 + lc * 2;
                float2 v = make_float2(acc[mt][nt][i2 * 2], acc[mt][nt][i2 * 2 + 1]);
                if (mode == 0) {
                    const int which = c >> 10, cc = c & 1023;
                    const int h = cc >> 6, d0 = cc & 63;
                    const int b = r >> 11, tg = r & 2047, g = tg >> 8, t = tg & 255;
                    float* base = (which == 0) ? g_q : (which == 1) ? g_k : g_v;
                    *reinterpret_cast<float2*>(
                        base + ((((size_t)b * NH + h) * NG + g) * GT + t) * HS + d0) = v;
                } else {
                    *reinterpret_cast<float2*>(Cout + (size_t)r * N + c) = v;
                }
            }
        }
    }
}

// ---------------- HMMA flash attention over 257 tokens ----------------
#define KS_OFF  0
#define KS_STR  68
#define VT_OFF  17476
#define VT_STR  264
#define STR_OFF 34372
#define QM_OFF  43076
#define WB_OFF  43144
#define ATT_F   43408

__global__ __launch_bounds__(256)
void attn_kernel() {
    extern __shared__ float sm[];
    const int id = blockIdx.x;
    const int g = id & 7, h = (id >> 3) & 15, b = id >> 7;
    const int tid = threadIdx.x;
    const int warp = tid >> 5, lane = tid & 31;
    const int lr = lane >> 2, lc = lane & 3;

    const size_t off = (size_t)id * (GT * HS);

    for (int idx = tid; idx < GT * HS; idx += 256) {
        int t = idx >> 6, d = idx & 63;
        sm[KS_OFF + t * KS_STR + kperm(d)] = tf32r(g_k[off + idx]);
        sm[VT_OFF + d * VT_STR + kperm(t)] = tf32r(g_v[off + idx]);
    }
    __syncthreads();

    {
        int which = tid >> 6;
        int d = tid & 63;
        if (which == 0) {
            float s = 0.f;
#pragma unroll 8
            for (int t = 0; t < GT; t++) s += g_q[off + t * HS + d];
            float m = s * (1.f / 256.f);
            g_qm[(size_t)id * HS + d] = m;
            sm[QM_OFF + kperm(d)] = tf32r(m);
        } else if (which == 1) {
            float s = 0.f;
#pragma unroll 8
            for (int t = 0; t < GT; t++) s += g_k[off + t * HS + d];
            float m = s * (1.f / 256.f);
            g_km[(size_t)id * HS + d] = m;
            sm[KS_OFF + 256 * KS_STR + kperm(d)] = tf32r(m);
        } else if (which == 2) {
            float s = 0.f;
            const float* vp = sm + VT_OFF + d * VT_STR;
#pragma unroll 16
            for (int t = 0; t < GT; t += 4) {
                float4 v = *reinterpret_cast<const float4*>(vp + t);
                s += v.x + v.y + v.z + v.w;
            }
            float m = s * (1.f / 256.f);
            sm[VT_OFF + d * VT_STR + 256] = tf32r(m);
#pragma unroll
            for (int p = 1; p < 8; p++) sm[VT_OFF + d * VT_STR + 256 + p] = 0.f;
        }
    }

    float* strip = sm + STR_OFF + warp * 16 * KS_STR;

#pragma unroll 1
    for (int qt = 0; qt < 2; qt++) {
        const int qb = qt * 128;
        const int r0 = qb + warp * 16 + lr;
        const int nchunks = qt ? 4 : 2;

        float qa[8][4];
        const float* qrow0 = g_q + off + (size_t)r0 * HS;
        const float* qrow1 = qrow0 + 8 * HS;
#pragma unroll
        for (int ds = 0; ds < 8; ds++) {
            qa[ds][0] = tf32r(qrow0[ds * 8 + lc]);
            qa[ds][1] = tf32r(qrow1[ds * 8 + lc]);
            qa[ds][2] = tf32r(qrow0[ds * 8 + lc + 4]);
            qa[ds][3] = tf32r(qrow1[ds * 8 + lc + 4]);
        }

        float m0 = -1e30f, m1 = -1e30f, l0 = 0.f, l1 = 0.f;
        float o[8][4];
#pragma unroll
        for (int nt = 0; nt < 8; nt++)
#pragma unroll
            for (int i = 0; i < 4; i++) o[nt][i] = 0.f;

#pragma unroll 1
        for (int kc = 0; kc < nchunks; kc++) {
            const int kbase = kc * 64;

            float s[8][4];
#pragma unroll
            for (int nt = 0; nt < 8; nt++) { s[nt][0] = s[nt][1] = s[nt][2] = s[nt][3] = 0.f; }
#pragma unroll
            for (int nt = 0; nt < 8; nt++) {
                const float* krow = sm + KS_OFF + (kbase + nt * 8 + lr) * KS_STR;
#pragma unroll
                for (int ds = 0; ds < 8; ds++) {
                    float2 bv = *reinterpret_cast<const float2*>(krow + ds * 8 + 2 * lc);
                    mma_tf32(s[nt][0], s[nt][1], s[nt][2], s[nt][3],
                             qa[ds][0], qa[ds][1], qa[ds][2], qa[ds][3], bv.x, bv.y);
                }
            }

            float mx0 = -1e30f, mx1 = -1e30f;
#pragma unroll
            for (int nt = 0; nt < 8; nt++) {
                const int j0 = kbase + nt * 8 + 2 * lc;
                const int j1 = j0 + 1;
                float v0 = s[nt][0] * 0.125f; if (j0 > r0)     v0 = -1e30f;
                float v1 = s[nt][1] * 0.125f; if (j1 > r0)     v1 = -1e30f;
                float v2 = s[nt][2] * 0.125f; if (j0 > r0 + 8) v2 = -1e30f;
                float v3 = s[nt][3] * 0.125f; if (j1 > r0 + 8) v3 = -1e30f;
                s[nt][0] = v0; s[nt][1] = v1; s[nt][2] = v2; s[nt][3] = v3;
                mx0 = fmaxf(mx0, fmaxf(v0, v1));
                mx1 = fmaxf(mx1, fmaxf(v2, v3));
            }
            mx0 = fmaxf(mx0, __shfl_xor_sync(0xffffffffu, mx0, 1));
            mx0 = fmaxf(mx0, __shfl_xor_sync(0xffffffffu, mx0, 2));
            mx1 = fmaxf(mx1, __shfl_xor_sync(0xffffffffu, mx1, 1));
            mx1 = fmaxf(mx1, __shfl_xor_sync(0xffffffffu, mx1, 2));

            const float nm0 = fmaxf(m0, mx0);
            const float nm1 = fmaxf(m1, mx1);
            const float f0 = __expf(m0 - nm0);
            const float f1 = __expf(m1 - nm1);
            m0 = nm0; m1 = nm1;

            float rs0 = 0.f, rs1 = 0.f;
#pragma unroll
            for (int nt = 0; nt < 8; nt++) {
                float p0 = __expf(s[nt][0] - nm0);
                float p1 = __expf(s[nt][1] - nm0);
                float p2 = __expf(s[nt][2] - nm1);
                float p3 = __expf(s[nt][3] - nm1);
                rs0 += p0 + p1; rs1 += p2 + p3;
                const int c0 = nt * 8 + perm8(2 * lc);
                const int c1 = nt * 8 + perm8(2 * lc + 1);
                strip[lr * KS_STR + c0]       = tf32r(p0);
                strip[lr * KS_STR + c1]       = tf32r(p1);
                strip[(lr + 8) * KS_STR + c0] = tf32r(p2);
                strip[(lr + 8) * KS_STR + c1] = tf32r(p3);
            }
            rs0 += __shfl_xor_sync(0xffffffffu, rs0, 1);
            rs0 += __shfl_xor_sync(0xffffffffu, rs0, 2);
            rs1 += __shfl_xor_sync(0xffffffffu, rs1, 1);
            rs1 += __shfl_xor_sync(0xffffffffu, rs1, 2);
            l0 = l0 * f0 + rs0;
            l1 = l1 * f1 + rs1;
#pragma unroll
            for (int nt = 0; nt < 8; nt++) {
                o[nt][0] *= f0; o[nt][1] *= f0;
                o[nt][2] *= f1; o[nt][3] *= f1;
            }
            __syncwarp();

            float pa[8][4];
#pragma unroll
            for (int ks = 0; ks < 8; ks++) {
                float2 lo = *reinterpret_cast<const float2*>(strip + lr * KS_STR + ks * 8 + 2 * lc);
                float2 hi = *reinterpret_cast<const float2*>(strip + (lr + 8) * KS_STR + ks * 8 + 2 * lc);
                pa[ks][0] = lo.x; pa[ks][1] = hi.x; pa[ks][2] = lo.y; pa[ks][3] = hi.y;
            }
#pragma unroll
            for (int nt = 0; nt < 8; nt++) {
                const float* vrow = sm + VT_OFF + (nt * 8 + lr) * VT_STR + kbase;
#pragma unroll
                for (int ks = 0; ks < 8; ks++) {
                    float2 bv = *reinterpret_cast<const float2*>(vrow + ks * 8 + 2 * lc);
                    mma_tf32(o[nt][0], o[nt][1], o[nt][2], o[nt][3],
                             pa[ks][0], pa[ks][1], pa[ks][2], pa[ks][3], bv.x, bv.y);
                }
            }
            __syncwarp();
        }

        // finalize: write plain fp16 h_xo (proj GEMM's A operand)
        const float inv0 = 1.f / l0;
        const float inv1 = 1.f / l1;
        __half* x0 = h_xo + ((size_t)b * T_ + g * GT + r0) * C_ + h * HS;
        __half* x1 = x0 + (size_t)8 * C_;
#pragma unroll
        for (int nt = 0; nt < 8; nt++) {
            const int p = nt * 8 + 2 * lc;
            *reinterpret_cast<__half2*>(x0 + p) = __floats2half2_rn(o[nt][0] * inv0, o[nt][1] * inv0);
            *reinterpret_cast<__half2*>(x1 + p) = __floats2half2_rn(o[nt][2] * inv1, o[nt][3] * inv1);
        }
    }

    __syncthreads();

    if (warp == 0) {
        float* wbuf = sm + WB_OFF;
        if (lane < 7) wbuf[257 + lane] = 0.f;
        const float* qm = sm + QM_OFF;
        float mx = -1e30f;
        float sc[9];
        for (int j = lane, u = 0; j < LQ; j += 32, u++) {
            const float4* kp = reinterpret_cast<const float4*>(sm + KS_OFF + j * KS_STR);
            const float4* qp = reinterpret_cast<const float4*>(qm);
            float s = 0.f;
#pragma unroll
            for (int dd = 0; dd < 16; dd++) {
                float4 kv = kp[dd], qv = qp[dd];
                s += qv.x * kv.x + qv.y * kv.y + qv.z * kv.z + qv.w * kv.w;
            }
            s *= 0.125f;
            sc[u] = s;
            mx = fmaxf(mx, s);
        }
#pragma unroll
        for (int o2 = 16; o2; o2 >>= 1) mx = fmaxf(mx, __shfl_xor_sync(0xffffffffu, mx, o2));
        float sum = 0.f;
        for (int j = lane, u = 0; j < LQ; j += 32, u++) {
            float e = __expf(sc[u] - mx);
            wbuf[kperm(j)] = e;
            sum += e;
        }
#pragma unroll
        for (int o2 = 16; o2; o2 >>= 1) sum += __shfl_xor_sync(0xffffffffu, sum, o2);
        const float inv = 1.f / sum;
        __syncwarp();
#pragma unroll
        for (int dh = 0; dh < 2; dh++) {
            const int d = lane + dh * 32;
            const float* vp = sm + VT_OFF + d * VT_STR;
            float acc = 0.f;
#pragma unroll 8
            for (int j = 0; j < 264; j += 4) {
                float4 w = *reinterpret_cast<const float4*>(wbuf + j);
                float4 v = *reinterpret_cast<const float4*>(vp + j);
                acc += w.x * v.x + w.y * v.y + w.z * v.z + w.w * v.w;
            }
            g_attm[(size_t)id * HS + d] = acc * inv;
        }
    }
}

// ---------------- level-2 tiny 7x7 causal attention + y outputs ----------------
__global__ void second_kernel(float* __restrict__ out) {
    __shared__ float q7[7][64], k7[7][64], a7[7][64];
    __shared__ float S[7][8], W[7][8];
    const int id = blockIdx.x;
    const int tid = threadIdx.x;

    for (int idx = tid; idx < 7 * 64; idx += 64) {
        int j = idx >> 6, d = idx & 63;
        q7[j][d] = g_qm[((size_t)id * NG + j) * HS + d];
        k7[j][d] = g_km[((size_t)id * NG + j) * HS + d];
        a7[j][d] = g_attm[((size_t)id * NG + j) * HS + d];
    }
    __syncthreads();

    if (tid < 28) {
        int p = tid, j = 0;
        while ((j + 1) * (j + 2) / 2 <= p) j++;
        int jp = p - j * (j + 1) / 2;
        float s = 0.f;
#pragma unroll
        for (int dd = 0; dd < 64; dd++) s += q7[j][dd] * k7[jp][dd];
        S[j][jp] = s * 0.125f;
    }
    __syncthreads();

    if (tid < 7) {
        int j = tid;
        float mx = -1e30f;
        for (int jp = 0; jp <= j; jp++) mx = fmaxf(mx, S[j][jp]);
        float sum = 0.f;
        for (int jp = 0; jp <= j; jp++) { float e = __expf(S[j][jp] - mx); W[j][jp] = e; sum += e; }
        float inv = 1.f / sum;
        for (int jp = 0; jp <= j; jp++) W[j][jp] *= inv;
    }
    __syncthreads();

    const size_t yq_off = (size_t)B_ * T_ * C_;
    const size_t ylen   = (size_t)B_ * NH * 7 * HS;
    int d = tid;
    for (int j = 0; j < 7; j++) {
        float acc = 0.f;
        for (int jp = 0; jp <= j; jp++) acc += W[j][jp] * a7[jp][d];
        size_t o = ((size_t)id * 7 + j) * HS + d;
        out[yq_off            + o] = q7[j][d];
        out[yq_off +     ylen + o] = k7[j][d];
        out[yq_off + 2 * ylen + o] = acc;
    }
}

// ---------------- launch ----------------
extern "C" void kernel_launch(void* const* d_in, const int* in_sizes, int n_in,
                              void* d_out, int out_size) {
    (void)in_sizes; (void)n_in; (void)out_size;
    const float* x      = (const float*)d_in[0];
    const float* W_attn = (const float*)d_in[1];
    const float* W_proj = (const float*)d_in[2];
    float* out = (float*)d_out;

    cvt_x_kernel<<<B_*T_*C_/2048, 256>>>(x);
    cvt_W_kernel<<<dim3(96, 32), 256>>>(W_attn, 3 * C_, 1);
    cvt_W_kernel<<<dim3(32, 32), 256>>>(W_proj, C_, 2);

    const int gemm_smem = STAGES * STG_BYTES;   // 65536
    cudaFuncSetAttribute(gemm_f16_kernel, cudaFuncAttributeMaxDynamicSharedMemorySize, gemm_smem);

    // qkv = x @ W_attn  (M=16384, N=3072)
    gemm_f16_kernel<<<dim3(128, 24), 256, gemm_smem>>>(nullptr, 0);

    const int att_smem = ATT_F * (int)sizeof(float);
    cudaFuncSetAttribute(attn_kernel, cudaFuncAttributeMaxDynamicSharedMemorySize, att_smem);
    attn_kernel<<<B_ * NH * NG, 256, att_smem>>>();

    second_kernel<<<B_ * NH, 64>>>(out);

    // out = xo @ W_proj  (M=16384, N=1024)
    gemm_f16_kernel<<<dim3(128, 8), 256, gemm_smem>>>(out, 1);
}

// round 14
// speedup vs baseline: 1.4840x; 1.2189x over previous
#include <cuda_runtime.h>
#include <cuda_fp16.h>
#include <cstdint>

#define B_  8
#define T_  2048
#define C_  1024
#define NH  16
#define HS  64
#define NG  8
#define GT  256
#define LQ  257

// ---------------- device scratch ----------------
__device__ float g_q[B_*NH*NG*GT*HS];
__device__ float g_k[B_*NH*NG*GT*HS];
__device__ float g_v[B_*NH*NG*GT*HS];
__device__ float g_qm[B_*NH*NG*HS];
__device__ float g_km[B_*NH*NG*HS];
__device__ float g_vm[B_*NH*NG*HS];
__device__ float g_attm[B_*NH*NG*HS];
__device__ __half h_xr[B_*T_*C_];         // x, fp16 plain row-major
__device__ __half h_xo[B_*T_*C_];         // attn out, fp16 plain row-major
__device__ __half h_War[3*C_*C_];         // W_attn^T [3072][1024] fp16
__device__ __half h_WpR[C_*C_];           // W_proj^T [1024][1024] fp16

__device__ __forceinline__ uint32_t smem_u32(const void* p) {
    uint32_t a;
    asm("{ .reg .u64 t; cvta.to.shared.u64 t, %1; cvt.u32.u64 %0, t; }" : "=r"(a) : "l"(p));
    return a;
}

__device__ __forceinline__ void cp16(uint32_t dst, const void* src) {
    asm volatile("cp.async.cg.shared.global [%0], [%1], 16;\n" :: "r"(dst), "l"(src));
}
#define CP_COMMIT() asm volatile("cp.async.commit_group;\n" ::: "memory")
#define CP_WAIT(n)  asm volatile("cp.async.wait_group %0;\n" :: "n"(n) : "memory")

__device__ __forceinline__ void ldmx4(uint32_t* r, uint32_t addr) {
    asm volatile("ldmatrix.sync.aligned.m8n8.x4.shared.b16 {%0,%1,%2,%3}, [%4];"
                 : "=r"(r[0]), "=r"(r[1]), "=r"(r[2]), "=r"(r[3]) : "r"(addr));
}

__device__ __forceinline__ void mma_f16(float& c0, float& c1, float& c2, float& c3,
                                        uint32_t a0, uint32_t a1, uint32_t a2, uint32_t a3,
                                        uint32_t b0, uint32_t b1) {
    asm volatile(
        "mma.sync.aligned.m16n8k16.row.col.f32.f16.f16.f32 "
        "{%0,%1,%2,%3}, {%4,%5,%6,%7}, {%8,%9}, {%0,%1,%2,%3};\n"
        : "+f"(c0), "+f"(c1), "+f"(c2), "+f"(c3)
        : "r"(a0), "r"(a1), "r"(a2), "r"(a3), "r"(b0), "r"(b1));
}

__device__ __forceinline__ uint32_t packh2(float a, float b) {
    __half2 h = __floats2half2_rn(a, b);
    return *reinterpret_cast<uint32_t*>(&h);
}

// ---------------- conversion kernels ----------------
__global__ void cvt_x_kernel(const float* __restrict__ src) {
    size_t base = ((size_t)blockIdx.x * 256 + threadIdx.x) * 8;
    float4 v0 = *reinterpret_cast<const float4*>(src + base);
    float4 v1 = *reinterpret_cast<const float4*>(src + base + 4);
    __half2 h[4];
    h[0] = __floats2half2_rn(v0.x, v0.y);
    h[1] = __floats2half2_rn(v0.z, v0.w);
    h[2] = __floats2half2_rn(v1.x, v1.y);
    h[3] = __floats2half2_rn(v1.z, v1.w);
    *reinterpret_cast<uint4*>(h_xr + base) = *reinterpret_cast<uint4*>(h);
}

__global__ void cvt_W_kernel(const float* __restrict__ W, int N, int which) {
    __half* Wt = (which == 1) ? h_War : h_WpR;
    __shared__ float tile[32][33];
    int bx = blockIdx.x * 32;
    int by = blockIdx.y * 32;
    int tx = threadIdx.x & 31, ty = threadIdx.x >> 5;
#pragma unroll
    for (int yy = ty; yy < 32; yy += 8)
        tile[yy][tx] = W[(size_t)(by + yy) * N + bx + tx];
    __syncthreads();
#pragma unroll
    for (int yy = ty; yy < 32; yy += 8) {
        int n = bx + yy, k = by + tx;
        Wt[(size_t)n * 1024 + k] = __float2half_rn(tile[tx][yy]);
    }
}

// ---------------- fp16 GEMM (unchanged from round 13) ----------------
#define BK 32
#define KCHUNKS 32
#define STAGES 4
#define STG_BYTES 16384

__global__ __launch_bounds__(256, 2)
void gemm_f16_kernel(float* __restrict__ Cout, int mode) {
    extern __shared__ __align__(16) char smc[];
    const uint32_t stg_b = smem_u32(smc);

    const __half* __restrict__ Ah = (mode == 0) ? h_xr  : h_xo;
    const __half* __restrict__ Bh = (mode == 0) ? h_War : h_WpR;

    const int tid  = threadIdx.x;
    const int warp = tid >> 5;
    const int lane = tid & 31;
    const int wm   = warp & 1;
    const int wn   = warp >> 1;
    const int bm   = blockIdx.x * 128;
    const int bn   = blockIdx.y * 128;

    float acc[4][4][4];
#pragma unroll
    for (int mt = 0; mt < 4; mt++)
#pragma unroll
        for (int nt = 0; nt < 4; nt++)
#pragma unroll
            for (int i = 0; i < 4; i++) acc[mt][nt][i] = 0.f;

    const int crow = tid >> 1;
    const int cg0  = (tid & 1) * 2;
    const int csw  = (crow >> 1) & 3;

    auto issue_copy = [&](int c, int s) {
        const int k0 = c * BK;
        const uint32_t sa = stg_b + (uint32_t)(s * STG_BYTES);
        const uint32_t sb = sa + 8192u;
        const __half* Asrc = Ah + (size_t)(bm + crow) * 1024 + k0;
        const __half* Bsrc = Bh + (size_t)(bn + crow) * 1024 + k0;
#pragma unroll
        for (int u = 0; u < 2; u++) {
            int g = cg0 + u;
            uint32_t d = (uint32_t)(crow * 64 + ((g ^ csw) << 4));
            cp16(sa + d, Asrc + g * 8);
            cp16(sb + d, Bsrc + g * 8);
        }
        CP_COMMIT();
    };

    issue_copy(0, 0);
    issue_copy(1, 1);
    issue_copy(2, 2);

    const int t8 = lane & 7;
    const int j  = lane >> 3;
    const int sw = t8 >> 1;
    const int arow_base = wm * 64 + 8 * (j & 1) + t8;
    const int brow_base = wn * 32 + 8 * (j >> 1) + t8;
    const int agr = j >> 1;
    const int bgr = j & 1;

    int stage = 0;
    for (int c = 0; c < KCHUNKS; c++) {
        if (c + 2 < KCHUNKS)      { CP_WAIT(2); }
        else if (c + 1 < KCHUNKS) { CP_WAIT(1); }
        else                      { CP_WAIT(0); }
        __syncthreads();

        if (c + 3 < KCHUNKS) {
            int ns = stage + 3; if (ns >= STAGES) ns -= STAGES;
            issue_copy(c + 3, ns);
        }

        const uint32_t As = stg_b + (uint32_t)(stage * STG_BYTES);
        const uint32_t Bs = As + 8192u;

#pragma unroll
        for (int g16 = 0; g16 < 2; g16++) {
            uint32_t a[4][4], br[2][4];
#pragma unroll
            for (int mt = 0; mt < 4; mt++)
                ldmx4(a[mt], As + (uint32_t)((arow_base + mt * 16) * 64
                                             + (((2 * g16 + agr) ^ sw) << 4)));
#pragma unroll
            for (int ntp = 0; ntp < 2; ntp++)
                ldmx4(br[ntp], Bs + (uint32_t)((brow_base + ntp * 16) * 64
                                               + (((2 * g16 + bgr) ^ sw) << 4)));
#pragma unroll
            for (int mt = 0; mt < 4; mt++)
#pragma unroll
                for (int nt = 0; nt < 4; nt++)
                    mma_f16(acc[mt][nt][0], acc[mt][nt][1], acc[mt][nt][2], acc[mt][nt][3],
                            a[mt][0], a[mt][1], a[mt][2], a[mt][3],
                            br[nt >> 1][2 * (nt & 1)], br[nt >> 1][2 * (nt & 1) + 1]);
        }
        stage++; if (stage >= STAGES) stage = 0;
    }

    const int lr = lane >> 2;
    const int lc = lane & 3;
    const int N = (mode == 0) ? 3 * C_ : C_;
#pragma unroll
    for (int mt = 0; mt < 4; mt++) {
#pragma unroll
        for (int i2 = 0; i2 < 2; i2++) {
            const int r = bm + wm * 64 + mt * 16 + lr + i2 * 8;
#pragma unroll
            for (int nt = 0; nt < 4; nt++) {
                const int c = bn + wn * 32 + nt * 8 + lc * 2;
                float2 v = make_float2(acc[mt][nt][i2 * 2], acc[mt][nt][i2 * 2 + 1]);
                if (mode == 0) {
                    const int which = c >> 10, cc = c & 1023;
                    const int h = cc >> 6, d0 = cc & 63;
                    const int b = r >> 11, tg = r & 2047, g = tg >> 8, t = tg & 255;
                    float* base = (which == 0) ? g_q : (which == 1) ? g_k : g_v;
                    *reinterpret_cast<float2*>(
                        base + ((((size_t)b * NH + h) * NG + g) * GT + t) * HS + d0) = v;
                } else {
                    *reinterpret_cast<float2*>(Cout + (size_t)r * N + c) = v;
                }
            }
        }
    }
}

// ---------------- fp16 flash attention, P-in-registers ----------------
// Ks [257][72] fp16 (37008 B) | Vt [64][264] fp16 (33792 B) | qm f32[64] | wbuf f32[264]
#define KS_B    0
#define KS_STR  72
#define VT_B    37008
#define VT_STR  264
#define QM_B    70800
#define WB_B    71056
#define ATT_BYTES 72112

__global__ __launch_bounds__(256, 2)
void attn_kernel() {
    extern __shared__ __align__(16) char smb[];
    __half* Ks  = reinterpret_cast<__half*>(smb + KS_B);
    __half* Vt  = reinterpret_cast<__half*>(smb + VT_B);
    float*  qmf = reinterpret_cast<float*>(smb + QM_B);
    float*  wbuf = reinterpret_cast<float*>(smb + WB_B);
    const uint32_t ks_b = smem_u32(Ks);
    const uint32_t vt_b = smem_u32(Vt);

    const int id = blockIdx.x;
    const int g = id & 7, h = (id >> 3) & 15, b = id >> 7;
    const int tid = threadIdx.x;
    const int warp = tid >> 5, lane = tid & 31;
    const int lr = lane >> 2, lc = lane & 3;
    const int t8 = lane & 7, jj = lane >> 3;

    const size_t off = (size_t)id * (GT * HS);

    // phase 0: K and V^T to fp16 smem
    for (int idx = tid; idx < GT * HS; idx += 256) {
        int t = idx >> 6, d = idx & 63;
        Ks[t * KS_STR + d] = __float2half_rn(g_k[off + idx]);
        Vt[d * VT_STR + t] = __float2half_rn(g_v[off + idx]);
    }
    __syncthreads();

    // phase 1: means (row/col 256; not read by main tiles)
    {
        int which = tid >> 6;
        int d = tid & 63;
        if (which == 0) {
            float s = 0.f;
#pragma unroll 8
            for (int t = 0; t < GT; t++) s += g_q[off + t * HS + d];
            float m = s * (1.f / 256.f);
            g_qm[(size_t)id * HS + d] = m;
            qmf[d] = m;
        } else if (which == 1) {
            float s = 0.f;
#pragma unroll 8
            for (int t = 0; t < GT; t++) s += g_k[off + t * HS + d];
            float m = s * (1.f / 256.f);
            g_km[(size_t)id * HS + d] = m;
            Ks[256 * KS_STR + d] = __float2half_rn(m);
        } else if (which == 2) {
            float s = 0.f;
#pragma unroll 8
            for (int t = 0; t < GT; t++) s += g_v[off + t * HS + d];
            float m = s * (1.f / 256.f);
            Vt[d * VT_STR + 256] = __float2half_rn(m);
#pragma unroll
            for (int p = 1; p < 8; p++) Vt[d * VT_STR + 256 + p] = __float2half_rn(0.f);
        }
    }

    // phase 2: two query tiles of 128 rows; warp owns 16 rows
#pragma unroll 1
    for (int qt = 0; qt < 2; qt++) {
        const int r0 = qt * 128 + warp * 16 + lr;
        const int nchunks = qt ? 4 : 2;

        // Q A-fragments (fp16, from gmem)
        uint32_t qa[4][4];
        const float* qrow0 = g_q + off + (size_t)r0 * HS;
        const float* qrow1 = qrow0 + 8 * HS;
#pragma unroll
        for (int g16 = 0; g16 < 4; g16++) {
            float2 v;
            v = *reinterpret_cast<const float2*>(qrow0 + 16 * g16 + 2 * lc);
            qa[g16][0] = packh2(v.x, v.y);
            v = *reinterpret_cast<const float2*>(qrow1 + 16 * g16 + 2 * lc);
            qa[g16][1] = packh2(v.x, v.y);
            v = *reinterpret_cast<const float2*>(qrow0 + 16 * g16 + 8 + 2 * lc);
            qa[g16][2] = packh2(v.x, v.y);
            v = *reinterpret_cast<const float2*>(qrow1 + 16 * g16 + 8 + 2 * lc);
            qa[g16][3] = packh2(v.x, v.y);
        }

        float m0 = -1e30f, m1 = -1e30f, l0 = 0.f, l1 = 0.f;
        float o[8][4];
#pragma unroll
        for (int nt = 0; nt < 8; nt++)
#pragma unroll
            for (int i = 0; i < 4; i++) o[nt][i] = 0.f;

#pragma unroll 1
        for (int kc = 0; kc < nchunks; kc++) {
            const int kbase = kc * 64;

            // ---- QK^T (fp16): S chunk 16x64 ----
            float s[8][4];
#pragma unroll
            for (int nt = 0; nt < 8; nt++) { s[nt][0] = s[nt][1] = s[nt][2] = s[nt][3] = 0.f; }
#pragma unroll
            for (int g16 = 0; g16 < 4; g16++) {
#pragma unroll
                for (int ntp = 0; ntp < 4; ntp++) {
                    uint32_t bk[4];
                    ldmx4(bk, ks_b + (uint32_t)(((kbase + ntp * 16 + t8 + 8 * (jj >> 1)) * KS_STR
                                                 + 16 * g16 + 8 * (jj & 1)) * 2));
                    mma_f16(s[2 * ntp][0], s[2 * ntp][1], s[2 * ntp][2], s[2 * ntp][3],
                            qa[g16][0], qa[g16][1], qa[g16][2], qa[g16][3], bk[0], bk[1]);
                    mma_f16(s[2 * ntp + 1][0], s[2 * ntp + 1][1], s[2 * ntp + 1][2], s[2 * ntp + 1][3],
                            qa[g16][0], qa[g16][1], qa[g16][2], qa[g16][3], bk[2], bk[3]);
                }
            }

            // ---- mask + scale + online softmax ----
            float mx0 = -1e30f, mx1 = -1e30f;
#pragma unroll
            for (int nt = 0; nt < 8; nt++) {
                const int j0 = kbase + nt * 8 + 2 * lc;
                const int j1 = j0 + 1;
                float v0 = s[nt][0] * 0.125f; if (j0 > r0)     v0 = -1e30f;
                float v1 = s[nt][1] * 0.125f; if (j1 > r0)     v1 = -1e30f;
                float v2 = s[nt][2] * 0.125f; if (j0 > r0 + 8) v2 = -1e30f;
                float v3 = s[nt][3] * 0.125f; if (j1 > r0 + 8) v3 = -1e30f;
                s[nt][0] = v0; s[nt][1] = v1; s[nt][2] = v2; s[nt][3] = v3;
                mx0 = fmaxf(mx0, fmaxf(v0, v1));
                mx1 = fmaxf(mx1, fmaxf(v2, v3));
            }
            mx0 = fmaxf(mx0, __shfl_xor_sync(0xffffffffu, mx0, 1));
            mx0 = fmaxf(mx0, __shfl_xor_sync(0xffffffffu, mx0, 2));
            mx1 = fmaxf(mx1, __shfl_xor_sync(0xffffffffu, mx1, 1));
            mx1 = fmaxf(mx1, __shfl_xor_sync(0xffffffffu, mx1, 2));

            const float nm0 = fmaxf(m0, mx0);
            const float nm1 = fmaxf(m1, mx1);
            const float f0 = __expf(m0 - nm0);
            const float f1 = __expf(m1 - nm1);
            m0 = nm0; m1 = nm1;

            float rs0 = 0.f, rs1 = 0.f;
#pragma unroll
            for (int nt = 0; nt < 8; nt++) {
                s[nt][0] = __expf(s[nt][0] - nm0);
                s[nt][1] = __expf(s[nt][1] - nm0);
                s[nt][2] = __expf(s[nt][2] - nm1);
                s[nt][3] = __expf(s[nt][3] - nm1);
                rs0 += s[nt][0] + s[nt][1];
                rs1 += s[nt][2] + s[nt][3];
            }
            rs0 += __shfl_xor_sync(0xffffffffu, rs0, 1);
            rs0 += __shfl_xor_sync(0xffffffffu, rs0, 2);
            rs1 += __shfl_xor_sync(0xffffffffu, rs1, 1);
            rs1 += __shfl_xor_sync(0xffffffffu, rs1, 2);
            l0 = l0 * f0 + rs0;
            l1 = l1 * f1 + rs1;

            // pack P into A-fragments (S frag layout == A frag layout for fp16!)
            uint32_t pa[4][4];
#pragma unroll
            for (int g16 = 0; g16 < 4; g16++) {
                pa[g16][0] = packh2(s[2 * g16][0], s[2 * g16][1]);
                pa[g16][1] = packh2(s[2 * g16][2], s[2 * g16][3]);
                pa[g16][2] = packh2(s[2 * g16 + 1][0], s[2 * g16 + 1][1]);
                pa[g16][3] = packh2(s[2 * g16 + 1][2], s[2 * g16 + 1][3]);
            }

#pragma unroll
            for (int nt = 0; nt < 8; nt++) {
                o[nt][0] *= f0; o[nt][1] *= f0;
                o[nt][2] *= f1; o[nt][3] *= f1;
            }

            // ---- PV (fp16): O += P @ V ----
#pragma unroll
            for (int g16 = 0; g16 < 4; g16++) {
#pragma unroll
                for (int dtp = 0; dtp < 4; dtp++) {
                    uint32_t bv[4];
                    ldmx4(bv, vt_b + (uint32_t)(((dtp * 16 + t8 + 8 * (jj >> 1)) * VT_STR
                                                 + kbase + 16 * g16 + 8 * (jj & 1)) * 2));
                    mma_f16(o[2 * dtp][0], o[2 * dtp][1], o[2 * dtp][2], o[2 * dtp][3],
                            pa[g16][0], pa[g16][1], pa[g16][2], pa[g16][3], bv[0], bv[1]);
                    mma_f16(o[2 * dtp + 1][0], o[2 * dtp + 1][1], o[2 * dtp + 1][2], o[2 * dtp + 1][3],
                            pa[g16][0], pa[g16][1], pa[g16][2], pa[g16][3], bv[2], bv[3]);
                }
            }
        }

        // finalize: write plain fp16 h_xo
        const float inv0 = 1.f / l0;
        const float inv1 = 1.f / l1;
        __half* x0 = h_xo + ((size_t)b * T_ + g * GT + r0) * C_ + h * HS;
        __half* x1 = x0 + (size_t)8 * C_;
#pragma unroll
        for (int nt = 0; nt < 8; nt++) {
            const int p = nt * 8 + 2 * lc;
            *reinterpret_cast<__half2*>(x0 + p) = __floats2half2_rn(o[nt][0] * inv0, o[nt][1] * inv0);
            *reinterpret_cast<__half2*>(x1 + p) = __floats2half2_rn(o[nt][2] * inv1, o[nt][3] * inv1);
        }
    }

    __syncthreads();

    // phase 3: mean-query (row 256) scalar path, warp 0
    if (warp == 0) {
        if (lane < 7) wbuf[257 + lane] = 0.f;
        float mx = -1e30f;
        float sc[9];
        for (int j = lane, u = 0; j < LQ; j += 32, u++) {
            const __half2* kp = reinterpret_cast<const __half2*>(Ks + j * KS_STR);
            float s = 0.f;
#pragma unroll
            for (int dd = 0; dd < 32; dd++) {
                float2 kv = __half22float2(kp[dd]);
                s += qmf[2 * dd] * kv.x + qmf[2 * dd + 1] * kv.y;
            }
            s *= 0.125f;
            sc[u] = s;
            mx = fmaxf(mx, s);
        }
#pragma unroll
        for (int o2 = 16; o2; o2 >>= 1) mx = fmaxf(mx, __shfl_xor_sync(0xffffffffu, mx, o2));
        float sum = 0.f;
        for (int j = lane, u = 0; j < LQ; j += 32, u++) {
            float e = __expf(sc[u] - mx);
            wbuf[j] = e;
            sum += e;
        }
#pragma unroll
        for (int o2 = 16; o2; o2 >>= 1) sum += __shfl_xor_sync(0xffffffffu, sum, o2);
        const float inv = 1.f / sum;
        __syncwarp();
#pragma unroll
        for (int dh = 0; dh < 2; dh++) {
            const int d = lane + dh * 32;
            const __half2* vp = reinterpret_cast<const __half2*>(Vt + d * VT_STR);
            float acc = 0.f;
#pragma unroll 4
            for (int j = 0; j < 132; j++) {
                float2 v = __half22float2(vp[j]);
                acc += wbuf[2 * j] * v.x + wbuf[2 * j + 1] * v.y;
            }
            g_attm[(size_t)id * HS + d] = acc * inv;
        }
    }
}

// ---------------- level-2 tiny 7x7 causal attention + y outputs ----------------
__global__ void second_kernel(float* __restrict__ out) {
    __shared__ float q7[7][64], k7[7][64], a7[7][64];
    __shared__ float S[7][8], W[7][8];
    const int id = blockIdx.x;
    const int tid = threadIdx.x;

    for (int idx = tid; idx < 7 * 64; idx += 64) {
        int j = idx >> 6, d = idx & 63;
        q7[j][d] = g_qm[((size_t)id * NG + j) * HS + d];
        k7[j][d] = g_km[((size_t)id * NG + j) * HS + d];
        a7[j][d] = g_attm[((size_t)id * NG + j) * HS + d];
    }
    __syncthreads();

    if (tid < 28) {
        int p = tid, j = 0;
        while ((j + 1) * (j + 2) / 2 <= p) j++;
        int jp = p - j * (j + 1) / 2;
        float s = 0.f;
#pragma unroll
        for (int dd = 0; dd < 64; dd++) s += q7[j][dd] * k7[jp][dd];
        S[j][jp] = s * 0.125f;
    }
    __syncthreads();

    if (tid < 7) {
        int j = tid;
        float mx = -1e30f;
        for (int jp = 0; jp <= j; jp++) mx = fmaxf(mx, S[j][jp]);
        float sum = 0.f;
        for (int jp = 0; jp <= j; jp++) { float e = __expf(S[j][jp] - mx); W[j][jp] = e; sum += e; }
        float inv = 1.f / sum;
        for (int jp = 0; jp <= j; jp++) W[j][jp] *= inv;
    }
    __syncthreads();

    const size_t yq_off = (size_t)B_ * T_ * C_;
    const size_t ylen   = (size_t)B_ * NH * 7 * HS;
    int d = tid;
    for (int j = 0; j < 7; j++) {
        float acc = 0.f;
        for (int jp = 0; jp <= j; jp++) acc += W[j][jp] * a7[jp][d];
        size_t o = ((size_t)id * 7 + j) * HS + d;
        out[yq_off            + o] = q7[j][d];
        out[yq_off +     ylen + o] = k7[j][d];
        out[yq_off + 2 * ylen + o] = acc;
    }
}

// ---------------- launch ----------------
extern "C" void kernel_launch(void* const* d_in, const int* in_sizes, int n_in,
                              void* d_out, int out_size) {
    (void)in_sizes; (void)n_in; (void)out_size;
    const float* x      = (const float*)d_in[0];
    const float* W_attn = (const float*)d_in[1];
    const float* W_proj = (const float*)d_in[2];
    float* out = (float*)d_out;

    cvt_x_kernel<<<B_*T_*C_/2048, 256>>>(x);
    cvt_W_kernel<<<dim3(96, 32), 256>>>(W_attn, 3 * C_, 1);
    cvt_W_kernel<<<dim3(32, 32), 256>>>(W_proj, C_, 2);

    const int gemm_smem = STAGES * STG_BYTES;   // 65536
    cudaFuncSetAttribute(gemm_f16_kernel, cudaFuncAttributeMaxDynamicSharedMemorySize, gemm_smem);

    // qkv = x @ W_attn  (M=16384, N=3072)
    gemm_f16_kernel<<<dim3(128, 24), 256, gemm_smem>>>(nullptr, 0);

    cudaFuncSetAttribute(attn_kernel, cudaFuncAttributeMaxDynamicSharedMemorySize, ATT_BYTES);
    attn_kernel<<<B_ * NH * NG, 256, ATT_BYTES>>>();

    second_kernel<<<B_ * NH, 64>>>(out);

    // out = xo @ W_proj  (M=16384, N=1024)
    gemm_f16_kernel<<<dim3(128, 8), 256, gemm_smem>>>(out, 1);
}

// round 15
// speedup vs baseline: 1.5403x; 1.0379x over previous
#include <cuda_runtime.h>
#include <cuda_fp16.h>
#include <cstdint>

#define B_  8
#define T_  2048
#define C_  1024
#define NH  16
#define HS  64
#define NG  8
#define GT  256
#define LQ  257

// ---------------- device scratch ----------------
__device__ __half h_q[B_*NH*NG*GT*HS];    // q/k/v now fp16 end-to-end
__device__ __half h_k[B_*NH*NG*GT*HS];
__device__ __half h_v[B_*NH*NG*GT*HS];
__device__ float g_qm[B_*NH*NG*HS];
__device__ float g_km[B_*NH*NG*HS];
__device__ float g_attm[B_*NH*NG*HS];
__device__ __half h_xr[B_*T_*C_];         // x, fp16 plain row-major
__device__ __half h_xo[B_*T_*C_];         // attn out, fp16 plain row-major
__device__ __half h_War[3*C_*C_];         // W_attn^T [3072][1024] fp16
__device__ __half h_WpR[C_*C_];           // W_proj^T [1024][1024] fp16

__device__ __forceinline__ uint32_t smem_u32(const void* p) {
    uint32_t a;
    asm("{ .reg .u64 t; cvta.to.shared.u64 t, %1; cvt.u32.u64 %0, t; }" : "=r"(a) : "l"(p));
    return a;
}

__device__ __forceinline__ void cp16(uint32_t dst, const void* src) {
    asm volatile("cp.async.cg.shared.global [%0], [%1], 16;\n" :: "r"(dst), "l"(src));
}
#define CP_COMMIT() asm volatile("cp.async.commit_group;\n" ::: "memory")
#define CP_WAIT(n)  asm volatile("cp.async.wait_group %0;\n" :: "n"(n) : "memory")

__device__ __forceinline__ void ldmx4(uint32_t* r, uint32_t addr) {
    asm volatile("ldmatrix.sync.aligned.m8n8.x4.shared.b16 {%0,%1,%2,%3}, [%4];"
                 : "=r"(r[0]), "=r"(r[1]), "=r"(r[2]), "=r"(r[3]) : "r"(addr));
}

__device__ __forceinline__ void mma_f16(float& c0, float& c1, float& c2, float& c3,
                                        uint32_t a0, uint32_t a1, uint32_t a2, uint32_t a3,
                                        uint32_t b0, uint32_t b1) {
    asm volatile(
        "mma.sync.aligned.m16n8k16.row.col.f32.f16.f16.f32 "
        "{%0,%1,%2,%3}, {%4,%5,%6,%7}, {%8,%9}, {%0,%1,%2,%3};\n"
        : "+f"(c0), "+f"(c1), "+f"(c2), "+f"(c3)
        : "r"(a0), "r"(a1), "r"(a2), "r"(a3), "r"(b0), "r"(b1));
}

__device__ __forceinline__ uint32_t packh2(float a, float b) {
    __half2 h = __floats2half2_rn(a, b);
    return *reinterpret_cast<uint32_t*>(&h);
}

// ---------------- conversion kernels ----------------
__global__ void cvt_x_kernel(const float* __restrict__ src) {
    size_t base = ((size_t)blockIdx.x * 256 + threadIdx.x) * 8;
    float4 v0 = *reinterpret_cast<const float4*>(src + base);
    float4 v1 = *reinterpret_cast<const float4*>(src + base + 4);
    __half2 h[4];
    h[0] = __floats2half2_rn(v0.x, v0.y);
    h[1] = __floats2half2_rn(v0.z, v0.w);
    h[2] = __floats2half2_rn(v1.x, v1.y);
    h[3] = __floats2half2_rn(v1.z, v1.w);
    *reinterpret_cast<uint4*>(h_xr + base) = *reinterpret_cast<uint4*>(h);
}

__global__ void cvt_W_kernel(const float* __restrict__ W, int N, int which) {
    __half* Wt = (which == 1) ? h_War : h_WpR;
    __shared__ float tile[32][33];
    int bx = blockIdx.x * 32;
    int by = blockIdx.y * 32;
    int tx = threadIdx.x & 31, ty = threadIdx.x >> 5;
#pragma unroll
    for (int yy = ty; yy < 32; yy += 8)
        tile[yy][tx] = W[(size_t)(by + yy) * N + bx + tx];
    __syncthreads();
#pragma unroll
    for (int yy = ty; yy < 32; yy += 8) {
        int n = bx + yy, k = by + tx;
        Wt[(size_t)n * 1024 + k] = __float2half_rn(tile[tx][yy]);
    }
}

// ---------------- fp16 GEMM: 128x128 CTA, 2x4 warps of 64x32, ldmatrix, 5 stages ----------------
#define BK 32
#define KCHUNKS 32
#define STAGES 5
#define STG_BYTES 16384

__global__ __launch_bounds__(256, 2)
void gemm_f16_kernel(float* __restrict__ Cout, int mode) {
    extern __shared__ __align__(16) char smc[];
    const uint32_t stg_b = smem_u32(smc);

    const __half* __restrict__ Ah = (mode == 0) ? h_xr  : h_xo;
    const __half* __restrict__ Bh = (mode == 0) ? h_War : h_WpR;

    const int tid  = threadIdx.x;
    const int warp = tid >> 5;
    const int lane = tid & 31;
    const int wm   = warp & 1;
    const int wn   = warp >> 1;
    const int bm   = blockIdx.x * 128;
    const int bn   = blockIdx.y * 128;

    float acc[4][4][4];
#pragma unroll
    for (int mt = 0; mt < 4; mt++)
#pragma unroll
        for (int nt = 0; nt < 4; nt++)
#pragma unroll
            for (int i = 0; i < 4; i++) acc[mt][nt][i] = 0.f;

    const int crow = tid >> 1;
    const int cg0  = (tid & 1) * 2;
    const int csw  = (crow >> 1) & 3;

    auto issue_copy = [&](int c, int s) {
        const int k0 = c * BK;
        const uint32_t sa = stg_b + (uint32_t)(s * STG_BYTES);
        const uint32_t sb = sa + 8192u;
        const __half* Asrc = Ah + (size_t)(bm + crow) * 1024 + k0;
        const __half* Bsrc = Bh + (size_t)(bn + crow) * 1024 + k0;
#pragma unroll
        for (int u = 0; u < 2; u++) {
            int g = cg0 + u;
            uint32_t d = (uint32_t)(crow * 64 + ((g ^ csw) << 4));
            cp16(sa + d, Asrc + g * 8);
            cp16(sb + d, Bsrc + g * 8);
        }
        CP_COMMIT();
    };

    issue_copy(0, 0);
    issue_copy(1, 1);
    issue_copy(2, 2);
    issue_copy(3, 3);

    const int t8 = lane & 7;
    const int j  = lane >> 3;
    const int sw = t8 >> 1;
    const int arow_base = wm * 64 + 8 * (j & 1) + t8;
    const int brow_base = wn * 32 + 8 * (j >> 1) + t8;
    const int agr = j >> 1;
    const int bgr = j & 1;

    int stage = 0;
    for (int c = 0; c < KCHUNKS; c++) {
        if (c + 3 < KCHUNKS)      { CP_WAIT(3); }
        else if (c + 2 < KCHUNKS) { CP_WAIT(2); }
        else if (c + 1 < KCHUNKS) { CP_WAIT(1); }
        else                      { CP_WAIT(0); }
        __syncthreads();

        if (c + 4 < KCHUNKS) {
            int ns = stage + 4; if (ns >= STAGES) ns -= STAGES;
            issue_copy(c + 4, ns);
        }

        const uint32_t As = stg_b + (uint32_t)(stage * STG_BYTES);
        const uint32_t Bs = As + 8192u;

#pragma unroll
        for (int g16 = 0; g16 < 2; g16++) {
            uint32_t a[4][4], br[2][4];
#pragma unroll
            for (int mt = 0; mt < 4; mt++)
                ldmx4(a[mt], As + (uint32_t)((arow_base + mt * 16) * 64
                                             + (((2 * g16 + agr) ^ sw) << 4)));
#pragma unroll
            for (int ntp = 0; ntp < 2; ntp++)
                ldmx4(br[ntp], Bs + (uint32_t)((brow_base + ntp * 16) * 64
                                               + (((2 * g16 + bgr) ^ sw) << 4)));
#pragma unroll
            for (int mt = 0; mt < 4; mt++)
#pragma unroll
                for (int nt = 0; nt < 4; nt++)
                    mma_f16(acc[mt][nt][0], acc[mt][nt][1], acc[mt][nt][2], acc[mt][nt][3],
                            a[mt][0], a[mt][1], a[mt][2], a[mt][3],
                            br[nt >> 1][2 * (nt & 1)], br[nt >> 1][2 * (nt & 1) + 1]);
        }
        stage++; if (stage >= STAGES) stage = 0;
    }

    const int lr = lane >> 2;
    const int lc = lane & 3;
    const int N = (mode == 0) ? 3 * C_ : C_;
#pragma unroll
    for (int mt = 0; mt < 4; mt++) {
#pragma unroll
        for (int i2 = 0; i2 < 2; i2++) {
            const int r = bm + wm * 64 + mt * 16 + lr + i2 * 8;
#pragma unroll
            for (int nt = 0; nt < 4; nt++) {
                const int c = bn + wn * 32 + nt * 8 + lc * 2;
                float2 v = make_float2(acc[mt][nt][i2 * 2], acc[mt][nt][i2 * 2 + 1]);
                if (mode == 0) {
                    const int which = c >> 10, cc = c & 1023;
                    const int h = cc >> 6, d0 = cc & 63;
                    const int b = r >> 11, tg = r & 2047, g = tg >> 8, t = tg & 255;
                    __half* base = (which == 0) ? h_q : (which == 1) ? h_k : h_v;
                    *reinterpret_cast<__half2*>(
                        base + ((((size_t)b * NH + h) * NG + g) * GT + t) * HS + d0) =
                        __floats2half2_rn(v.x, v.y);
                } else {
                    *reinterpret_cast<float2*>(Cout + (size_t)r * N + c) = v;
                }
            }
        }
    }
}

// ---------------- fp16 flash attention, P-in-registers ----------------
// Ks [257][72] fp16 | Vt [64][264] fp16 | qm f32[64] | wbuf f32[264]
#define KS_B    0
#define KS_STR  72
#define VT_B    37008
#define VT_STR  264
#define QM_B    70800
#define WB_B    71056
#define ATT_BYTES 72112

__global__ __launch_bounds__(256, 2)
void attn_kernel() {
    extern __shared__ __align__(16) char smb[];
    __half* Ks  = reinterpret_cast<__half*>(smb + KS_B);
    __half* Vt  = reinterpret_cast<__half*>(smb + VT_B);
    float*  qmf = reinterpret_cast<float*>(smb + QM_B);
    float*  wbuf = reinterpret_cast<float*>(smb + WB_B);
    const uint32_t ks_b = smem_u32(Ks);
    const uint32_t vt_b = smem_u32(Vt);

    const int id = blockIdx.x;
    const int g = id & 7, h = (id >> 3) & 15, b = id >> 7;
    const int tid = threadIdx.x;
    const int warp = tid >> 5, lane = tid & 31;
    const int lr = lane >> 2, lc = lane & 3;
    const int t8 = lane & 7, jj = lane >> 3;

    const size_t off = (size_t)id * (GT * HS);

    // phase 0: K and V^T to smem (fp16 source, half2 loads)
    {
        const __half2* kp = reinterpret_cast<const __half2*>(h_k + off);
        const __half2* vp = reinterpret_cast<const __half2*>(h_v + off);
        for (int idx = tid; idx < GT * HS / 2; idx += 256) {
            int t = idx >> 5, dh = idx & 31;
            *reinterpret_cast<__half2*>(Ks + t * KS_STR + 2 * dh) = kp[idx];
            __half2 vv = vp[idx];
            Vt[(2 * dh) * VT_STR + t]     = __low2half(vv);
            Vt[(2 * dh + 1) * VT_STR + t] = __high2half(vv);
        }
    }
    __syncthreads();

    // phase 1: means (row/col 256; not read by main tiles)
    {
        int which = tid >> 6;
        int d = tid & 63;
        if (which == 0) {
            float s = 0.f;
#pragma unroll 8
            for (int t = 0; t < GT; t++) s += __half2float(h_q[off + t * HS + d]);
            float m = s * (1.f / 256.f);
            g_qm[(size_t)id * HS + d] = m;
            qmf[d] = m;
        } else if (which == 1) {
            float s = 0.f;
#pragma unroll 8
            for (int t = 0; t < GT; t++) s += __half2float(h_k[off + t * HS + d]);
            float m = s * (1.f / 256.f);
            g_km[(size_t)id * HS + d] = m;
            Ks[256 * KS_STR + d] = __float2half_rn(m);
        } else if (which == 2) {
            float s = 0.f;
            const __half2* vrow = reinterpret_cast<const __half2*>(Vt + d * VT_STR);
#pragma unroll 8
            for (int t2 = 0; t2 < 128; t2++) {
                float2 v = __half22float2(vrow[t2]);
                s += v.x + v.y;
            }
            float m = s * (1.f / 256.f);
            Vt[d * VT_STR + 256] = __float2half_rn(m);
#pragma unroll
            for (int p = 1; p < 8; p++) Vt[d * VT_STR + 256 + p] = __float2half_rn(0.f);
        }
    }

    // phase 2: two query tiles of 128 rows; warp owns 16 rows
#pragma unroll 1
    for (int qt = 0; qt < 2; qt++) {
        const int r0 = qt * 128 + warp * 16 + lr;
        const int nchunks = qt ? 4 : 2;

        // Q A-fragments: direct 4-byte loads from fp16 h_q
        uint32_t qa[4][4];
        const __half* qrow0 = h_q + off + (size_t)r0 * HS;
        const __half* qrow1 = qrow0 + 8 * HS;
#pragma unroll
        for (int g16 = 0; g16 < 4; g16++) {
            qa[g16][0] = *reinterpret_cast<const uint32_t*>(qrow0 + 16 * g16 + 2 * lc);
            qa[g16][1] = *reinterpret_cast<const uint32_t*>(qrow1 + 16 * g16 + 2 * lc);
            qa[g16][2] = *reinterpret_cast<const uint32_t*>(qrow0 + 16 * g16 + 8 + 2 * lc);
            qa[g16][3] = *reinterpret_cast<const uint32_t*>(qrow1 + 16 * g16 + 8 + 2 * lc);
        }

        float m0 = -1e30f, m1 = -1e30f, l0 = 0.f, l1 = 0.f;
        float o[8][4];
#pragma unroll
        for (int nt = 0; nt < 8; nt++)
#pragma unroll
            for (int i = 0; i < 4; i++) o[nt][i] = 0.f;

#pragma unroll 1
        for (int kc = 0; kc < nchunks; kc++) {
            const int kbase = kc * 64;

            float s[8][4];
#pragma unroll
            for (int nt = 0; nt < 8; nt++) { s[nt][0] = s[nt][1] = s[nt][2] = s[nt][3] = 0.f; }
#pragma unroll
            for (int g16 = 0; g16 < 4; g16++) {
#pragma unroll
                for (int ntp = 0; ntp < 4; ntp++) {
                    uint32_t bk[4];
                    ldmx4(bk, ks_b + (uint32_t)(((kbase + ntp * 16 + t8 + 8 * (jj >> 1)) * KS_STR
                                                 + 16 * g16 + 8 * (jj & 1)) * 2));
                    mma_f16(s[2 * ntp][0], s[2 * ntp][1], s[2 * ntp][2], s[2 * ntp][3],
                            qa[g16][0], qa[g16][1], qa[g16][2], qa[g16][3], bk[0], bk[1]);
                    mma_f16(s[2 * ntp + 1][0], s[2 * ntp + 1][1], s[2 * ntp + 1][2], s[2 * ntp + 1][3],
                            qa[g16][0], qa[g16][1], qa[g16][2], qa[g16][3], bk[2], bk[3]);
                }
            }

            float mx0 = -1e30f, mx1 = -1e30f;
#pragma unroll
            for (int nt = 0; nt < 8; nt++) {
                const int j0 = kbase + nt * 8 + 2 * lc;
                const int j1 = j0 + 1;
                float v0 = s[nt][0] * 0.125f; if (j0 > r0)     v0 = -1e30f;
                float v1 = s[nt][1] * 0.125f; if (j1 > r0)     v1 = -1e30f;
                float v2 = s[nt][2] * 0.125f; if (j0 > r0 + 8) v2 = -1e30f;
                float v3 = s[nt][3] * 0.125f; if (j1 > r0 + 8) v3 = -1e30f;
                s[nt][0] = v0; s[nt][1] = v1; s[nt][2] = v2; s[nt][3] = v3;
                mx0 = fmaxf(mx0, fmaxf(v0, v1));
                mx1 = fmaxf(mx1, fmaxf(v2, v3));
            }
            mx0 = fmaxf(mx0, __shfl_xor_sync(0xffffffffu, mx0, 1));
            mx0 = fmaxf(mx0, __shfl_xor_sync(0xffffffffu, mx0, 2));
            mx1 = fmaxf(mx1, __shfl_xor_sync(0xffffffffu, mx1, 1));
            mx1 = fmaxf(mx1, __shfl_xor_sync(0xffffffffu, mx1, 2));

            const float nm0 = fmaxf(m0, mx0);
            const float nm1 = fmaxf(m1, mx1);
            const float f0 = __expf(m0 - nm0);
            const float f1 = __expf(m1 - nm1);
            m0 = nm0; m1 = nm1;

            float rs0 = 0.f, rs1 = 0.f;
#pragma unroll
            for (int nt = 0; nt < 8; nt++) {
                s[nt][0] = __expf(s[nt][0] - nm0);
                s[nt][1] = __expf(s[nt][1] - nm0);
                s[nt][2] = __expf(s[nt][2] - nm1);
                s[nt][3] = __expf(s[nt][3] - nm1);
                rs0 += s[nt][0] + s[nt][1];
                rs1 += s[nt][2] + s[nt][3];
            }
            rs0 += __shfl_xor_sync(0xffffffffu, rs0, 1);
            rs0 += __shfl_xor_sync(0xffffffffu, rs0, 2);
            rs1 += __shfl_xor_sync(0xffffffffu, rs1, 1);
            rs1 += __shfl_xor_sync(0xffffffffu, rs1, 2);
            l0 = l0 * f0 + rs0;
            l1 = l1 * f1 + rs1;

            uint32_t pa[4][4];
#pragma unroll
            for (int g16 = 0; g16 < 4; g16++) {
                pa[g16][0] = packh2(s[2 * g16][0], s[2 * g16][1]);
                pa[g16][1] = packh2(s[2 * g16][2], s[2 * g16][3]);
                pa[g16][2] = packh2(s[2 * g16 + 1][0], s[2 * g16 + 1][1]);
                pa[g16][3] = packh2(s[2 * g16 + 1][2], s[2 * g16 + 1][3]);
            }

#pragma unroll
            for (int nt = 0; nt < 8; nt++) {
                o[nt][0] *= f0; o[nt][1] *= f0;
                o[nt][2] *= f1; o[nt][3] *= f1;
            }

#pragma unroll
            for (int g16 = 0; g16 < 4; g16++) {
#pragma unroll
                for (int dtp = 0; dtp < 4; dtp++) {
                    uint32_t bv[4];
                    ldmx4(bv, vt_b + (uint32_t)(((dtp * 16 + t8 + 8 * (jj >> 1)) * VT_STR
                                                 + kbase + 16 * g16 + 8 * (jj & 1)) * 2));
                    mma_f16(o[2 * dtp][0], o[2 * dtp][1], o[2 * dtp][2], o[2 * dtp][3],
                            pa[g16][0], pa[g16][1], pa[g16][2], pa[g16][3], bv[0], bv[1]);
                    mma_f16(o[2 * dtp + 1][0], o[2 * dtp + 1][1], o[2 * dtp + 1][2], o[2 * dtp + 1][3],
                            pa[g16][0], pa[g16][1], pa[g16][2], pa[g16][3], bv[2], bv[3]);
                }
            }
        }

        const float inv0 = 1.f / l0;
        const float inv1 = 1.f / l1;
        __half* x0 = h_xo + ((size_t)b * T_ + g * GT + r0) * C_ + h * HS;
        __half* x1 = x0 + (size_t)8 * C_;
#pragma unroll
        for (int nt = 0; nt < 8; nt++) {
            const int p = nt * 8 + 2 * lc;
            *reinterpret_cast<__half2*>(x0 + p) = __floats2half2_rn(o[nt][0] * inv0, o[nt][1] * inv0);
            *reinterpret_cast<__half2*>(x1 + p) = __floats2half2_rn(o[nt][2] * inv1, o[nt][3] * inv1);
        }
    }

    __syncthreads();

    // phase 3: mean-query (row 256) scalar path, warp 0
    if (warp == 0) {
        if (lane < 7) wbuf[257 + lane] = 0.f;
        float mx = -1e30f;
        float sc[9];
        for (int j = lane, u = 0; j < LQ; j += 32, u++) {
            const __half2* kp = reinterpret_cast<const __half2*>(Ks + j * KS_STR);
            float s = 0.f;
#pragma unroll
            for (int dd = 0; dd < 32; dd++) {
                float2 kv = __half22float2(kp[dd]);
                s += qmf[2 * dd] * kv.x + qmf[2 * dd + 1] * kv.y;
            }
            s *= 0.125f;
            sc[u] = s;
            mx = fmaxf(mx, s);
        }
#pragma unroll
        for (int o2 = 16; o2; o2 >>= 1) mx = fmaxf(mx, __shfl_xor_sync(0xffffffffu, mx, o2));
        float sum = 0.f;
        for (int j = lane, u = 0; j < LQ; j += 32, u++) {
            float e = __expf(sc[u] - mx);
            wbuf[j] = e;
            sum += e;
        }
#pragma unroll
        for (int o2 = 16; o2; o2 >>= 1) sum += __shfl_xor_sync(0xffffffffu, sum, o2);
        const float inv = 1.f / sum;
        __syncwarp();
#pragma unroll
        for (int dh = 0; dh < 2; dh++) {
            const int d = lane + dh * 32;
            const __half2* vp = reinterpret_cast<const __half2*>(Vt + d * VT_STR);
            float acc = 0.f;
#pragma unroll 4
            for (int j = 0; j < 132; j++) {
                float2 v = __half22float2(vp[j]);
                acc += wbuf[2 * j] * v.x + wbuf[2 * j + 1] * v.y;
            }
            g_attm[(size_t)id * HS + d] = acc * inv;
        }
    }
}

// ---------------- level-2 tiny 7x7 causal attention + y outputs ----------------
__global__ void second_kernel(float* __restrict__ out) {
    __shared__ float q7[7][64], k7[7][64], a7[7][64];
    __shared__ float S[7][8], W[7][8];
    const int id = blockIdx.x;
    const int tid = threadIdx.x;

    for (int idx = tid; idx < 7 * 64; idx += 64) {
        int j = idx >> 6, d = idx & 63;
        q7[j][d] = g_qm[((size_t)id * NG + j) * HS + d];
        k7[j][d] = g_km[((size_t)id * NG + j) * HS + d];
        a7[j][d] = g_attm[((size_t)id * NG + j) * HS + d];
    }
    __syncthreads();

    if (tid < 28) {
        int p = tid, j = 0;
        while ((j + 1) * (j + 2) / 2 <= p) j++;
        int jp = p - j * (j + 1) / 2;
        float s = 0.f;
#pragma unroll
        for (int dd = 0; dd < 64; dd++) s += q7[j][dd] * k7[jp][dd];
        S[j][jp] = s * 0.125f;
    }
    __syncthreads();

    if (tid < 7) {
        int j = tid;
        float mx = -1e30f;
        for (int jp = 0; jp <= j; jp++) mx = fmaxf(mx, S[j][jp]);
        float sum = 0.f;
        for (int jp = 0; jp <= j; jp++) { float e = __expf(S[j][jp] - mx); W[j][jp] = e; sum += e; }
        float inv = 1.f / sum;
        for (int jp = 0; jp <= j; jp++) W[j][jp] *= inv;
    }
    __syncthreads();

    const size_t yq_off = (size_t)B_ * T_ * C_;
    const size_t ylen   = (size_t)B_ * NH * 7 * HS;
    int d = tid;
    for (int j = 0; j < 7; j++) {
        float acc = 0.f;
        for (int jp = 0; jp <= j; jp++) acc += W[j][jp] * a7[jp][d];
        size_t o = ((size_t)id * 7 + j) * HS + d;
        out[yq_off            + o] = q7[j][d];
        out[yq_off +     ylen + o] = k7[j][d];
        out[yq_off + 2 * ylen + o] = acc;
    }
}

// ---------------- launch ----------------
extern "C" void kernel_launch(void* const* d_in, const int* in_sizes, int n_in,
                              void* d_out, int out_size) {
    (void)in_sizes; (void)n_in; (void)out_size;
    const float* x      = (const float*)d_in[0];
    const float* W_attn = (const float*)d_in[1];
    const float* W_proj = (const float*)d_in[2];
    float* out = (float*)d_out;

    cvt_x_kernel<<<B_*T_*C_/2048, 256>>>(x);
    cvt_W_kernel<<<dim3(96, 32), 256>>>(W_attn, 3 * C_, 1);
    cvt_W_kernel<<<dim3(32, 32), 256>>>(W_proj, C_, 2);

    const int gemm_smem = STAGES * STG_BYTES;   // 81920
    cudaFuncSetAttribute(gemm_f16_kernel, cudaFuncAttributeMaxDynamicSharedMemorySize, gemm_smem);

    // qkv = x @ W_attn  (M=16384, N=3072)
    gemm_f16_kernel<<<dim3(128, 24), 256, gemm_smem>>>(nullptr, 0);

    cudaFuncSetAttribute(attn_kernel, cudaFuncAttributeMaxDynamicSharedMemorySize, ATT_BYTES);
    attn_kernel<<<B_ * NH * NG, 256, ATT_BYTES>>>();

    second_kernel<<<B_ * NH, 64>>>(out);

    // out = xo @ W_proj  (M=16384, N=1024)
    gemm_f16_kernel<<<dim3(128, 8), 256, gemm_smem>>>(out, 1);
}